// round 3
// baseline (speedup 1.0000x reference)
#include <cuda_runtime.h>

#define NELEC 16
#define NNUC  4
#define DDIM  128
#define KDIM  64
#define FDIM  32
#define HDIM  45
#define E0    112
#define E1    128
#define E2    64
#define ETOT  304
#define TPB   320

// ---- shared memory layout (float offsets) ----
#define OFF_ELEC 0                         // 16*128
#define OFF_HX   2048                      // 2*16*65
#define OFF_WEH  (OFF_HX + 2*16*65)        // 304*65
#define OFF_Z    (OFF_WEH + 304*65)        // 16*65
#define OFF_W1   (OFF_Z + 16*65)           // 3*32*45
#define OFF_B1   (OFF_W1 + 3*32*45)        // 3*48 (padded rows)
#define OFF_W2   (OFF_B1 + 3*48)           // 3*45*64
#define OFF_GH   (OFF_W2 + 3*45*64)        // 128*64 shared buffer (hW or gW)
#define OFF_NUC  (OFF_GH + 8192)           // 4*65
#define OFF_D    (OFF_NUC + 4*65)          // 304
#define OFF_SEND (OFF_D + 304)             // 304 (ints)
#define OFF_RS   (OFF_SEND + 304)          // 16*3
#define OFF_CO   (OFF_RS + 48)             // 4*3
#define SMEM_FLOATS (OFF_CO + 12)
#define SMEM_BYTES (SMEM_FLOATS * 4)

// receiver CSR, rebuilt every launch (deterministic)
__device__ int g_deg[3][NELEC];
__device__ int g_edge[3][NELEC][8];

__global__ void csr_kernel(const int* __restrict__ same_r,
                           const int* __restrict__ anti_r,
                           const int* __restrict__ ne_r) {
    if (blockIdx.x == 0 && threadIdx.x == 0) {
        for (int j = 0; j < 3; j++)
            for (int r = 0; r < NELEC; r++) g_deg[j][r] = 0;
        for (int e = 0; e < E0; e++) {
            int r = same_r[e]; int c = g_deg[0][r];
            if (c < 8) g_edge[0][r][c] = e;
            g_deg[0][r] = c + 1;
        }
        for (int e = 0; e < E1; e++) {
            int r = anti_r[e]; int c = g_deg[1][r];
            if (c < 8) g_edge[1][r][c] = E0 + e;
            g_deg[1][r] = c + 1;
        }
        for (int e = 0; e < E2; e++) {
            int r = ne_r[e]; int c = g_deg[2][r];
            if (c < 8) g_edge[2][r][c] = E0 + E1 + e;
            g_deg[2][r] = c + 1;
        }
    }
}

__global__ __launch_bounds__(TPB, 1)
void schnet_kernel(const float* __restrict__ rs, const float* __restrict__ coords,
                   const float* __restrict__ Xtab, const float* __restrict__ Yw,
                   const float* __restrict__ wW1, const float* __restrict__ wb1,
                   const float* __restrict__ wW2, const float* __restrict__ h0tab,
                   const float* __restrict__ hW, const float* __restrict__ gW,
                   const int* __restrict__ same_s, const int* __restrict__ same_r,
                   const int* __restrict__ anti_s, const int* __restrict__ anti_r,
                   const int* __restrict__ ne_s, const int* __restrict__ ne_r,
                   float* __restrict__ out) {
    extern __shared__ float sm[];
    const int tid = threadIdx.x;
    const int b = blockIdx.x;

    float* s_elec = sm + OFF_ELEC;
    float* s_hx   = sm + OFF_HX;
    float* s_weh  = sm + OFF_WEH;
    float* s_z    = sm + OFF_Z;
    float* s_W1   = sm + OFF_W1;
    float* s_b1   = sm + OFF_B1;
    float* s_W2   = sm + OFF_W2;
    float* s_gh   = sm + OFF_GH;
    float* s_nuc  = sm + OFF_NUC;
    float* s_d    = sm + OFF_D;
    int*   s_send = (int*)(sm + OFF_SEND);
    float* s_rs   = sm + OFF_RS;
    float* s_co   = sm + OFF_CO;

    // ---- block init: positions, embeddings, senders ----
    for (int i = tid; i < NELEC * 3; i += TPB) s_rs[i] = rs[b * NELEC * 3 + i];
    for (int i = tid; i < NNUC * 3; i += TPB) s_co[i] = coords[i];
    for (int i = tid; i < NELEC * DDIM; i += TPB) s_elec[i] = Xtab[i & (DDIM - 1)];
    for (int i = tid; i < NNUC * KDIM; i += TPB)
        s_nuc[(i >> 6) * 65 + (i & 63)] = Yw[i];
    for (int i = tid; i < E0; i += TPB) s_send[i] = same_s[i];
    for (int i = tid; i < E1; i += TPB) s_send[E0 + i] = anti_s[i];
    for (int i = tid; i < E2; i += TPB) s_send[E0 + E1 + i] = ne_s[i];
    __syncthreads();

    // ---- edge distances ----
    for (int e = tid; e < ETOT; e += TPB) {
        int s = s_send[e];
        float ax, ay, az, bx, by, bz;
        if (e < E0 + E1) {
            int r = (e < E0) ? same_r[e] : anti_r[e - E0];
            ax = s_rs[s * 3 + 0]; ay = s_rs[s * 3 + 1]; az = s_rs[s * 3 + 2];
            bx = s_rs[r * 3 + 0]; by = s_rs[r * 3 + 1]; bz = s_rs[r * 3 + 2];
        } else {
            int r = ne_r[e - E0 - E1];
            ax = s_co[s * 3 + 0]; ay = s_co[s * 3 + 1]; az = s_co[s * 3 + 2];
            bx = s_rs[r * 3 + 0]; by = s_rs[r * 3 + 1]; bz = s_rs[r * 3 + 2];
        }
        float dx = ax - bx, dy = ay - by, dz = az - bz;
        s_d[e] = sqrtf(dx * dx + dy * dy + dz * dz);
    }
    __syncthreads();

    // ================= layer loop =================
    for (int l = 0; l < 3; l++) {
        // ---- hx (sender features) for j = 0,1 ----
        if (l == 0) {
            // h0_tab[j][0][k] broadcast to all electrons
            for (int i = tid; i < 2 * NELEC * KDIM; i += TPB) {
                int j = i >> 10, r = (i >> 6) & 15, k = i & 63;
                s_hx[(j * NELEC + r) * 65 + k] = h0tab[j * KDIM + k];
            }
            __syncthreads();
        } else {
            for (int j = 0; j < 2; j++) {
                for (int i = tid; i < DDIM * KDIM; i += TPB)
                    s_gh[i] = hW[((l - 1) * 2 + j) * DDIM * KDIM + i];
                __syncthreads();
                if (tid < 256) {
                    int r = tid >> 4, kg = tid & 15;
                    float a0 = 0.f, a1 = 0.f, a2 = 0.f, a3 = 0.f;
                    const float* er = s_elec + r * DDIM;
                    for (int dd = 0; dd < DDIM; dd++) {
                        float ev = er[dd];
                        float4 w = ((const float4*)(s_gh + dd * KDIM))[kg];
                        a0 += ev * w.x; a1 += ev * w.y;
                        a2 += ev * w.z; a3 += ev * w.w;
                    }
                    float* dst = s_hx + (j * NELEC + r) * 65 + kg * 4;
                    dst[0] = a0; dst[1] = a1; dst[2] = a2; dst[3] = a3;
                }
                __syncthreads();
            }
        }

        // ---- stage MLP weights for this layer (all 3 j) ----
        for (int i = tid; i < 3 * FDIM * HDIM; i += TPB)
            s_W1[i] = wW1[l * 3 * FDIM * HDIM + i];
        for (int i = tid; i < 3 * HDIM; i += TPB)
            s_b1[(i / HDIM) * 48 + (i % HDIM)] = wb1[l * 3 * HDIM + i];
        for (int i = tid; i < 3 * HDIM * KDIM; i += TPB)
            s_W2[i] = wW2[l * 3 * HDIM * KDIM + i];
        __syncthreads();

        // ---- per-edge MLP, 2 same-j edges per thread (weight-LDS reuse) ----
        if (tid < 152) {
            int j, eA, eB;
            if (tid < 56)       { j = 0; eA = tid;               eB = eA + 56; }
            else if (tid < 120) { j = 1; eA = 112 + (tid - 56);  eB = eA + 64; }
            else                { j = 2; eA = 240 + (tid - 120); eB = eA + 32; }

            float dA = s_d[eA], dB = s_d[eB];
            float envA = dA * dA * __expf(-dA);
            float envB = dB * dB * __expf(-dB);
            const float* W1  = s_W1 + j * (FDIM * HDIM);
            const float* B1c = s_b1 + j * 48;
            const float* W2  = s_W2 + j * (HDIM * KDIM);

            float hidA[HDIM], hidB[HDIM];
#pragma unroll
            for (int h = 0; h < HDIM; h++) { float bb = B1c[h]; hidA[h] = bb; hidB[h] = bb; }

            for (int f = 0; f < FDIM; f++) {
                float q  = f * (1.0f / 31.0f);
                float mu = 10.0f * q * q;
                float sg = (1.0f + 10.0f * q) * (1.0f / 7.0f);
                float inv2 = 1.0f / (sg * sg);
                float tA = dA - mu, tB = dB - mu;
                float fA = envA * __expf(-tA * tA * inv2);
                float fB = envB * __expf(-tB * tB * inv2);
                const float* w1f = W1 + f * HDIM;
#pragma unroll
                for (int h = 0; h < HDIM; h++) {
                    float w = w1f[h];
                    hidA[h] += fA * w;
                    hidB[h] += fB * w;
                }
            }
#pragma unroll
            for (int h = 0; h < HDIM; h++) {
                float xA = hidA[h]; hidA[h] = xA / (1.0f + __expf(-xA));
                float xB = hidB[h]; hidB[h] = xB / (1.0f + __expf(-xB));
            }

            int sA = s_send[eA], sB = s_send[eB];
            const float* hxA = (j < 2) ? (s_hx + (j * NELEC + sA) * 65) : (s_nuc + sA * 65);
            const float* hxB = (j < 2) ? (s_hx + (j * NELEC + sB) * 65) : (s_nuc + sB * 65);
            float* oA = s_weh + eA * 65;
            float* oB = s_weh + eB * 65;
            for (int k = 0; k < KDIM; k++) {
                float wA = 0.f, wB = 0.f;
                const float* w2k = W2 + k;
#pragma unroll
                for (int h = 0; h < HDIM; h++) {
                    float w = w2k[h * KDIM];
                    wA += hidA[h] * w;
                    wB += hidB[h] * w;
                }
                oA[k] = wA * hxA[k];
                oB[k] = wB * hxB[k];
            }
        }
        __syncthreads();

        // ---- per j: stage gW + receiver gather, then z @ gW into elec ----
        for (int j = 0; j < 3; j++) {
            for (int i = tid; i < KDIM * DDIM; i += TPB)
                s_gh[i] = gW[(l * 3 + j) * KDIM * DDIM + i];
            for (int u = tid; u < NELEC * KDIM; u += TPB) {
                int r = u >> 6, k = u & 63;
                int dg = g_deg[j][r];
                float zv = 0.f;
                for (int i = 0; i < dg; i++)
                    zv += s_weh[g_edge[j][r][i] * 65 + k];
                s_z[r * 65 + k] = zv;
            }
            __syncthreads();
            if (tid < 256) {
                int r = tid >> 4, dg4 = tid & 15;
                float a0 = 0.f, a1 = 0.f, a2 = 0.f, a3 = 0.f;
                float a4 = 0.f, a5 = 0.f, a6 = 0.f, a7 = 0.f;
                const float* zr = s_z + r * 65;
                for (int k = 0; k < KDIM; k++) {
                    float zv = zr[k];
                    const float4* row = ((const float4*)(s_gh + k * DDIM)) + dg4 * 2;
                    float4 x = row[0], y = row[1];
                    a0 += zv * x.x; a1 += zv * x.y; a2 += zv * x.z; a3 += zv * x.w;
                    a4 += zv * y.x; a5 += zv * y.y; a6 += zv * y.z; a7 += zv * y.w;
                }
                float* dst = s_elec + r * DDIM + dg4 * 8;
                dst[0] += a0; dst[1] += a1; dst[2] += a2; dst[3] += a3;
                dst[4] += a4; dst[5] += a5; dst[6] += a6; dst[7] += a7;
            }
            __syncthreads();
        }
    }

    // ---- write result ----
    for (int i = tid; i < NELEC * DDIM; i += TPB)
        out[b * NELEC * DDIM + i] = s_elec[i];
}

extern "C" void kernel_launch(void* const* d_in, const int* in_sizes, int n_in,
                              void* d_out, int out_size) {
    const float* rs     = (const float*)d_in[0];
    const float* coords = (const float*)d_in[1];
    const float* Xtab   = (const float*)d_in[2];
    const float* Yw     = (const float*)d_in[3];
    const float* wW1    = (const float*)d_in[4];
    const float* wb1    = (const float*)d_in[5];
    const float* wW2    = (const float*)d_in[6];
    const float* h0tab  = (const float*)d_in[7];
    const float* hW     = (const float*)d_in[8];
    const float* gW     = (const float*)d_in[9];
    const int* same_s   = (const int*)d_in[10];
    const int* same_r   = (const int*)d_in[11];
    const int* anti_s   = (const int*)d_in[12];
    const int* anti_r   = (const int*)d_in[13];
    const int* ne_s     = (const int*)d_in[14];
    const int* ne_r     = (const int*)d_in[15];
    float* out = (float*)d_out;

    int B = in_sizes[0] / (NELEC * 3);

    cudaFuncSetAttribute(schnet_kernel,
                         cudaFuncAttributeMaxDynamicSharedMemorySize, SMEM_BYTES);

    csr_kernel<<<1, 32>>>(same_r, anti_r, ne_r);
    schnet_kernel<<<B, TPB, SMEM_BYTES>>>(rs, coords, Xtab, Yw, wW1, wb1, wW2,
                                          h0tab, hW, gW, same_s, same_r,
                                          anti_s, anti_r, ne_s, ne_r, out);
}

// round 5
// speedup vs baseline: 1.1808x; 1.1808x over previous
#include <cuda_runtime.h>

#define NELEC 16
#define NNUC  4
#define DDIM  128
#define KDIM  64
#define FDIM  32
#define HDIM  45
#define E0    112
#define E1    128
#define E2    64
#define ETOT  304
#define TPB   256

// ---- shared memory layout (float offsets) ----
#define OFF_ELEC 0                 // 16*128 = 2048
#define OFF_UPD  2048              // 16*128 = 2048
#define OFF_HX   4096              // 16*65  = 1040 (current j only)
#define OFF_WEH  5136              // 128*65 = 8320 (current j only)
#define OFF_Z    13456             // 16*65  = 1040
#define OFF_W1   14496             // 32*45  = 1440
#define OFF_B1   15936             // 48
#define OFF_W2   15984             // 45*64  = 2880
#define OFF_GH   18864             // 128*64 = 8192 (hW or gW buffer)
#define OFF_NUC  27056             // 4*65   = 260
#define OFF_D    27316             // 304
#define OFF_SEND 27620             // 304 (ints)
#define OFF_RS   27924             // 48
#define OFF_CO   27972             // 12
#define OFF_MU   27984             // 32
#define OFF_IV   28016             // 32
#define OFF_DEG  28048             // 3*16 ints
#define OFF_EDG  28096             // 3*16*8 ints
#define SMEM_FLOATS 28480
#define SMEM_BYTES (SMEM_FLOATS * 4)   // 113920 B -> 2 CTAs/SM

// receiver CSR (LOCAL per-j edge indices), rebuilt every launch
__device__ int g_deg[3][NELEC];
__device__ int g_edge[3][NELEC][8];

__global__ void csr_kernel(const int* __restrict__ same_r,
                           const int* __restrict__ anti_r,
                           const int* __restrict__ ne_r) {
    if (blockIdx.x == 0 && threadIdx.x == 0) {
        for (int j = 0; j < 3; j++)
            for (int r = 0; r < NELEC; r++) g_deg[j][r] = 0;
        for (int e = 0; e < E0; e++) {
            int r = same_r[e]; int c = g_deg[0][r];
            if (c < 8) g_edge[0][r][c] = e;
            g_deg[0][r] = c + 1;
        }
        for (int e = 0; e < E1; e++) {
            int r = anti_r[e]; int c = g_deg[1][r];
            if (c < 8) g_edge[1][r][c] = e;
            g_deg[1][r] = c + 1;
        }
        for (int e = 0; e < E2; e++) {
            int r = ne_r[e]; int c = g_deg[2][r];
            if (c < 8) g_edge[2][r][c] = e;
            g_deg[2][r] = c + 1;
        }
    }
}

__global__ __launch_bounds__(TPB, 2)
void schnet_kernel(const float* __restrict__ rs, const float* __restrict__ coords,
                   const float* __restrict__ Xtab, const float* __restrict__ Yw,
                   const float* __restrict__ wW1, const float* __restrict__ wb1,
                   const float* __restrict__ wW2, const float* __restrict__ h0tab,
                   const float* __restrict__ hW, const float* __restrict__ gW,
                   const int* __restrict__ same_s, const int* __restrict__ same_r,
                   const int* __restrict__ anti_s, const int* __restrict__ anti_r,
                   const int* __restrict__ ne_s, const int* __restrict__ ne_r,
                   float* __restrict__ out) {
    extern __shared__ float sm[];
    const int tid = threadIdx.x;
    const int b = blockIdx.x;

    float* s_elec = sm + OFF_ELEC;
    float* s_upd  = sm + OFF_UPD;
    float* s_hx   = sm + OFF_HX;
    float* s_weh  = sm + OFF_WEH;
    float* s_z    = sm + OFF_Z;
    float* s_W1   = sm + OFF_W1;
    float* s_b1   = sm + OFF_B1;
    float* s_W2   = sm + OFF_W2;
    float* s_gh   = sm + OFF_GH;
    float* s_nuc  = sm + OFF_NUC;
    float* s_d    = sm + OFF_D;
    int*   s_send = (int*)(sm + OFF_SEND);
    float* s_rs   = sm + OFF_RS;
    float* s_co   = sm + OFF_CO;
    float* s_mu   = sm + OFF_MU;
    float* s_iv   = sm + OFF_IV;
    int*   s_deg  = (int*)(sm + OFF_DEG);
    int*   s_edg  = (int*)(sm + OFF_EDG);

    // ---- block init ----
    for (int i = tid; i < NELEC * 3; i += TPB) s_rs[i] = rs[b * NELEC * 3 + i];
    for (int i = tid; i < NNUC * 3; i += TPB) s_co[i] = coords[i];
    for (int i = tid; i < NELEC * DDIM; i += TPB) s_elec[i] = Xtab[i & (DDIM - 1)];
    for (int i = tid; i < NNUC * KDIM; i += TPB)
        s_nuc[(i >> 6) * 65 + (i & 63)] = Yw[i];
    for (int i = tid; i < E0; i += TPB) s_send[i] = same_s[i];
    for (int i = tid; i < E1; i += TPB) s_send[E0 + i] = anti_s[i];
    for (int i = tid; i < E2; i += TPB) s_send[E0 + E1 + i] = ne_s[i];
    if (tid < FDIM) {
        float q = tid * (1.0f / 31.0f);
        float mu = 10.0f * q * q;
        float sg = (1.0f + 10.0f * q) * (1.0f / 7.0f);
        s_mu[tid] = mu;
        s_iv[tid] = 1.0f / (sg * sg);
    }
    for (int i = tid; i < 3 * NELEC; i += TPB) s_deg[i] = ((const int*)g_deg)[i];
    for (int i = tid; i < 3 * NELEC * 8; i += TPB) s_edg[i] = ((const int*)g_edge)[i];
    __syncthreads();

    // ---- edge distances ----
    for (int e = tid; e < ETOT; e += TPB) {
        int s = s_send[e];
        float ax, ay, az, bx, by, bz;
        if (e < E0 + E1) {
            int r = (e < E0) ? same_r[e] : anti_r[e - E0];
            ax = s_rs[s * 3 + 0]; ay = s_rs[s * 3 + 1]; az = s_rs[s * 3 + 2];
            bx = s_rs[r * 3 + 0]; by = s_rs[r * 3 + 1]; bz = s_rs[r * 3 + 2];
        } else {
            int r = ne_r[e - E0 - E1];
            ax = s_co[s * 3 + 0]; ay = s_co[s * 3 + 1]; az = s_co[s * 3 + 2];
            bx = s_rs[r * 3 + 0]; by = s_rs[r * 3 + 1]; bz = s_rs[r * 3 + 2];
        }
        float dx = ax - bx, dy = ay - by, dz = az - bz;
        s_d[e] = sqrtf(dx * dx + dy * dy + dz * dz);
    }
    __syncthreads();

    // ================= layer loop =================
    for (int l = 0; l < 3; l++) {
        // zero update accumulator (ordered by later syncs before first use)
        for (int i = tid; i < NELEC * DDIM; i += TPB) s_upd[i] = 0.0f;

        for (int j = 0; j < 3; j++) {
            int Ej, base, S;
            if (j == 0)      { Ej = E0; base = 0;       S = 2; }
            else if (j == 1) { Ej = E1; base = E0;      S = 2; }
            else             { Ej = E2; base = E0 + E1; S = 4; }
            const int Kper = KDIM / S;

            // ---- hx (sender features) for this j ----
            if (j < 2) {
                if (l == 0) {
                    // broadcast embedding; overlap with weight staging below
                    for (int i = tid; i < NELEC * KDIM; i += TPB)
                        s_hx[(i >> 6) * 65 + (i & 63)] = h0tab[j * KDIM + (i & 63)];
                } else {
                    for (int i = tid; i < DDIM * KDIM; i += TPB)
                        s_gh[i] = hW[((l - 1) * 2 + j) * DDIM * KDIM + i];
                    __syncthreads();
                    {
                        int r = tid >> 4, kg = tid & 15;
                        float a0 = 0.f, a1 = 0.f, a2 = 0.f, a3 = 0.f;
                        const float* er = s_elec + r * DDIM;
                        for (int dd = 0; dd < DDIM; dd++) {
                            float ev = er[dd];
                            float4 w = ((const float4*)(s_gh + dd * KDIM))[kg];
                            a0 += ev * w.x; a1 += ev * w.y;
                            a2 += ev * w.z; a3 += ev * w.w;
                        }
                        float* dst = s_hx + r * 65 + kg * 4;
                        dst[0] = a0; dst[1] = a1; dst[2] = a2; dst[3] = a3;
                    }
                    __syncthreads();
                }
            }

            // ---- stage W1/b1/W2 and gW for this (l,j) ----
            {
                int lj = l * 3 + j;
                for (int i = tid; i < FDIM * HDIM; i += TPB)
                    s_W1[i] = wW1[lj * FDIM * HDIM + i];
                if (tid < HDIM) s_b1[tid] = wb1[lj * HDIM + tid];
                for (int i = tid; i < HDIM * KDIM; i += TPB)
                    s_W2[i] = wW2[lj * HDIM * KDIM + i];
                for (int i = tid; i < KDIM * DDIM; i += TPB)
                    s_gh[i] = gW[lj * KDIM * DDIM + i];
            }
            __syncthreads();

            // ---- edge MLP, k-split across S threads per edge ----
            if (tid < Ej * S) {
                int e = tid % Ej;
                int half = tid / Ej;
                int ge = base + e;
                float d = s_d[ge];
                float env = d * d * __expf(-d);

                float hid[HDIM];
#pragma unroll
                for (int h = 0; h < HDIM; h++) hid[h] = s_b1[h];

#pragma unroll 4
                for (int f = 0; f < FDIM; f++) {
                    float t = d - s_mu[f];
                    float fe = env * __expf(-t * t * s_iv[f]);
                    const float* w1f = s_W1 + f * HDIM;
#pragma unroll
                    for (int h = 0; h < HDIM; h++) hid[h] += fe * w1f[h];
                }
#pragma unroll
                for (int h = 0; h < HDIM; h++) {
                    float x = hid[h];
                    hid[h] = __fdividef(x, 1.0f + __expf(-x));
                }

                int snd = s_send[ge];
                const float* hx = ((j < 2) ? s_hx : s_nuc) + snd * 65 + half * Kper;
                const float* W2c = s_W2 + half * Kper;
                float* o = s_weh + e * 65 + half * Kper;
                for (int kk = 0; kk < Kper; kk++) {
                    float acc = 0.f;
                    const float* w2k = W2c + kk;
#pragma unroll
                    for (int h = 0; h < HDIM; h++) acc += hid[h] * w2k[h * KDIM];
                    o[kk] = acc * hx[kk];
                }
            }
            __syncthreads();

            // ---- receiver gather into z ----
            for (int u = tid; u < NELEC * KDIM; u += TPB) {
                int r = u >> 6, k = u & 63;
                int dg = s_deg[j * NELEC + r];
                const int* er = s_edg + (j * NELEC + r) * 8;
                float zv = 0.f;
                for (int i = 0; i < dg; i++)
                    zv += s_weh[er[i] * 65 + k];
                s_z[r * 65 + k] = zv;
            }
            __syncthreads();

            // ---- z @ gW accumulate into upd ----
            {
                int r = tid >> 4, dg4 = tid & 15;
                float a0 = 0.f, a1 = 0.f, a2 = 0.f, a3 = 0.f;
                float a4 = 0.f, a5 = 0.f, a6 = 0.f, a7 = 0.f;
                const float* zr = s_z + r * 65;
                for (int k = 0; k < KDIM; k++) {
                    float zv = zr[k];
                    const float4* row = ((const float4*)(s_gh + k * DDIM)) + dg4 * 2;
                    float4 x = row[0], y = row[1];
                    a0 += zv * x.x; a1 += zv * x.y; a2 += zv * x.z; a3 += zv * x.w;
                    a4 += zv * y.x; a5 += zv * y.y; a6 += zv * y.z; a7 += zv * y.w;
                }
                float* dst = s_upd + r * DDIM + dg4 * 8;
                dst[0] += a0; dst[1] += a1; dst[2] += a2; dst[3] += a3;
                dst[4] += a4; dst[5] += a5; dst[6] += a6; dst[7] += a7;
            }
            __syncthreads();
        }

        // ---- fold updates into elec (all j used start-of-layer elec) ----
        for (int i = tid; i < NELEC * DDIM; i += TPB) s_elec[i] += s_upd[i];
        __syncthreads();
    }

    // ---- write result ----
    for (int i = tid; i < NELEC * DDIM; i += TPB)
        out[b * NELEC * DDIM + i] = s_elec[i];
}

extern "C" void kernel_launch(void* const* d_in, const int* in_sizes, int n_in,
                              void* d_out, int out_size) {
    const float* rs     = (const float*)d_in[0];
    const float* coords = (const float*)d_in[1];
    const float* Xtab   = (const float*)d_in[2];
    const float* Yw     = (const float*)d_in[3];
    const float* wW1    = (const float*)d_in[4];
    const float* wb1    = (const float*)d_in[5];
    const float* wW2    = (const float*)d_in[6];
    const float* h0tab  = (const float*)d_in[7];
    const float* hW     = (const float*)d_in[8];
    const float* gW     = (const float*)d_in[9];
    const int* same_s   = (const int*)d_in[10];
    const int* same_r   = (const int*)d_in[11];
    const int* anti_s   = (const int*)d_in[12];
    const int* anti_r   = (const int*)d_in[13];
    const int* ne_s     = (const int*)d_in[14];
    const int* ne_r     = (const int*)d_in[15];
    float* out = (float*)d_out;

    int B = in_sizes[0] / (NELEC * 3);

    cudaFuncSetAttribute(schnet_kernel,
                         cudaFuncAttributeMaxDynamicSharedMemorySize, SMEM_BYTES);

    csr_kernel<<<1, 32>>>(same_r, anti_r, ne_r);
    schnet_kernel<<<B, TPB, SMEM_BYTES>>>(rs, coords, Xtab, Yw, wW1, wb1, wW2,
                                          h0tab, hW, gW, same_s, same_r,
                                          anti_s, anti_r, ne_s, ne_r, out);
}

// round 6
// speedup vs baseline: 1.3573x; 1.1495x over previous
#include <cuda_runtime.h>

typedef unsigned long long u64;

#define NELEC 16
#define NNUC  4
#define DDIM  128
#define KDIM  64
#define FDIM  32
#define HDIM  45
#define E0    112
#define E1    128
#define E2    64
#define ETOT  304
#define TPB   256
#define PAD   68   // row pad for weh/z/hx/nuc (float4-aligned, conflict-free)

// ---- shared memory layout (float offsets) ----
#define OFF_ELEC 0                  // 2048
#define OFF_HX   2048               // 16*68 = 1088
#define OFF_WEH  3136               // 128*68 = 8704
#define OFF_Z    11840              // 16*68 = 1088
#define OFF_W1   12928              // 32*48 = 1536 (padded rows, pad zeroed)
#define OFF_B1   14464              // 48 (pad zeroed)
#define OFF_W2T  14512              // 64*48 = 3072 (TRANSPOSED, pad zeroed)
#define OFF_GH   17584              // 128*64 = 8192 (gW buffer)
#define OFF_NUC  25776              // 4*68 = 272
#define OFF_D    26048              // 304
#define OFF_SEND 26352              // 304 ints
#define OFF_RS   26656              // 48
#define OFF_CO   26704              // 12
#define OFF_MU   26716              // 32
#define OFF_IV   26748              // 32
#define OFF_DEG  26780              // 48 ints
#define OFF_EDG  26828              // 384 ints
#define SMEM_FLOATS 27212
#define SMEM_BYTES (SMEM_FLOATS * 4)   // 108848 B -> 2 CTAs/SM

__device__ __forceinline__ u64 ffma2(u64 a, u64 b, u64 c) {
    u64 d; asm("fma.rn.f32x2 %0,%1,%2,%3;" : "=l"(d) : "l"(a), "l"(b), "l"(c)); return d;
}
__device__ __forceinline__ u64 fadd2(u64 a, u64 b) {
    u64 d; asm("add.rn.f32x2 %0,%1,%2;" : "=l"(d) : "l"(a), "l"(b)); return d;
}
__device__ __forceinline__ u64 pack2(float x, float y) {
    u64 r; asm("mov.b64 %0,{%1,%2};" : "=l"(r) : "f"(x), "f"(y)); return r;
}
__device__ __forceinline__ void unpack2(u64 v, float& x, float& y) {
    asm("mov.b64 {%0,%1},%2;" : "=f"(x), "=f"(y) : "l"(v));
}

// receiver CSR (LOCAL per-j edge indices), rebuilt every launch
__device__ int g_deg[3][NELEC];
__device__ int g_edge[3][NELEC][8];

__global__ void csr_kernel(const int* __restrict__ same_r,
                           const int* __restrict__ anti_r,
                           const int* __restrict__ ne_r) {
    if (blockIdx.x == 0 && threadIdx.x == 0) {
        for (int j = 0; j < 3; j++)
            for (int r = 0; r < NELEC; r++) g_deg[j][r] = 0;
        for (int e = 0; e < E0; e++) {
            int r = same_r[e]; int c = g_deg[0][r];
            if (c < 8) g_edge[0][r][c] = e;
            g_deg[0][r] = c + 1;
        }
        for (int e = 0; e < E1; e++) {
            int r = anti_r[e]; int c = g_deg[1][r];
            if (c < 8) g_edge[1][r][c] = e;
            g_deg[1][r] = c + 1;
        }
        for (int e = 0; e < E2; e++) {
            int r = ne_r[e]; int c = g_deg[2][r];
            if (c < 8) g_edge[2][r][c] = e;
            g_deg[2][r] = c + 1;
        }
    }
}

__global__ __launch_bounds__(TPB, 2)
void schnet_kernel(const float* __restrict__ rs, const float* __restrict__ coords,
                   const float* __restrict__ Xtab, const float* __restrict__ Yw,
                   const float* __restrict__ wW1, const float* __restrict__ wb1,
                   const float* __restrict__ wW2, const float* __restrict__ h0tab,
                   const float* __restrict__ hW, const float* __restrict__ gW,
                   const int* __restrict__ same_s, const int* __restrict__ same_r,
                   const int* __restrict__ anti_s, const int* __restrict__ anti_r,
                   const int* __restrict__ ne_s, const int* __restrict__ ne_r,
                   float* __restrict__ out) {
    extern __shared__ float sm[];
    const int tid = threadIdx.x;
    const int b = blockIdx.x;

    float* s_elec = sm + OFF_ELEC;
    float* s_hx   = sm + OFF_HX;
    float* s_weh  = sm + OFF_WEH;
    float* s_z    = sm + OFF_Z;
    float* s_W1   = sm + OFF_W1;
    float* s_b1   = sm + OFF_B1;
    float* s_W2t  = sm + OFF_W2T;
    float* s_gh   = sm + OFF_GH;
    float* s_nuc  = sm + OFF_NUC;
    float* s_d    = sm + OFF_D;
    int*   s_send = (int*)(sm + OFF_SEND);
    float* s_rs   = sm + OFF_RS;
    float* s_co   = sm + OFF_CO;
    float* s_mu   = sm + OFF_MU;
    float* s_iv   = sm + OFF_IV;
    int*   s_deg  = (int*)(sm + OFF_DEG);
    int*   s_edg  = (int*)(sm + OFF_EDG);

    // ---- block init ----
    for (int i = tid; i < NELEC * 3; i += TPB) s_rs[i] = rs[b * NELEC * 3 + i];
    for (int i = tid; i < NNUC * 3; i += TPB) s_co[i] = coords[i];
    for (int i = tid; i < NELEC * DDIM; i += TPB) s_elec[i] = Xtab[i & (DDIM - 1)];
    for (int i = tid; i < NNUC * KDIM; i += TPB)
        s_nuc[(i >> 6) * PAD + (i & 63)] = Yw[i];
    for (int i = tid; i < E0; i += TPB) s_send[i] = same_s[i];
    for (int i = tid; i < E1; i += TPB) s_send[E0 + i] = anti_s[i];
    for (int i = tid; i < E2; i += TPB) s_send[E0 + E1 + i] = ne_s[i];
    if (tid < FDIM) {
        float q = tid * (1.0f / 31.0f);
        float mu = 10.0f * q * q;
        float sg = (1.0f + 10.0f * q) * (1.0f / 7.0f);
        s_mu[tid] = mu;
        s_iv[tid] = 1.0f / (sg * sg);
    }
    for (int i = tid; i < 3 * NELEC; i += TPB) s_deg[i] = ((const int*)g_deg)[i];
    for (int i = tid; i < 3 * NELEC * 8; i += TPB) s_edg[i] = ((const int*)g_edge)[i];
    // zero pad lanes of W1/W2t/b1 once (staging never writes h>=45)
    for (int i = tid; i < FDIM; i += TPB) {
        s_W1[i * 48 + 45] = 0.f; s_W1[i * 48 + 46] = 0.f; s_W1[i * 48 + 47] = 0.f;
    }
    for (int i = tid; i < KDIM; i += TPB) {
        s_W2t[i * 48 + 45] = 0.f; s_W2t[i * 48 + 46] = 0.f; s_W2t[i * 48 + 47] = 0.f;
    }
    if (tid < 3) s_b1[45 + tid] = 0.f;
    __syncthreads();

    // ---- edge distances ----
    for (int e = tid; e < ETOT; e += TPB) {
        int s = s_send[e];
        float ax, ay, az, bx, by, bz;
        if (e < E0 + E1) {
            int r = (e < E0) ? same_r[e] : anti_r[e - E0];
            ax = s_rs[s * 3 + 0]; ay = s_rs[s * 3 + 1]; az = s_rs[s * 3 + 2];
            bx = s_rs[r * 3 + 0]; by = s_rs[r * 3 + 1]; bz = s_rs[r * 3 + 2];
        } else {
            int r = ne_r[e - E0 - E1];
            ax = s_co[s * 3 + 0]; ay = s_co[s * 3 + 1]; az = s_co[s * 3 + 2];
            bx = s_rs[r * 3 + 0]; by = s_rs[r * 3 + 1]; bz = s_rs[r * 3 + 2];
        }
        float dx = ax - bx, dy = ay - by, dz = az - bz;
        s_d[e] = sqrtf(dx * dx + dy * dy + dz * dz);
    }
    __syncthreads();

    const int rr = tid >> 4;      // 0..15 (receiver electron)
    const int cc = tid & 15;      // 0..15 (column group)

    // ================= layer loop =================
    for (int l = 0; l < 3; l++) {
        // per-layer update accumulators (packed pairs), j-invariant mapping
        u64 a0 = 0ULL, a1 = 0ULL, a2 = 0ULL, a3 = 0ULL;

        for (int j = 0; j < 3; j++) {
            int Ej, base, S;
            if (j == 0)      { Ej = E0; base = 0;       S = 2; }
            else if (j == 1) { Ej = E1; base = E0;      S = 2; }
            else             { Ej = E2; base = E0 + E1; S = 4; }
            const int Kper = KDIM / S;

            // ---- stage all weights for this (l,j); hW goes into weh (free now) ----
            {
                int lj = l * 3 + j;
                for (int i = tid; i < FDIM * HDIM; i += TPB) {
                    int f = i / HDIM, h = i - f * HDIM;
                    s_W1[f * 48 + h] = wW1[lj * FDIM * HDIM + i];
                }
                if (tid < HDIM) s_b1[tid] = wb1[lj * HDIM + tid];
                // transposed W2: read wW2[h][k] scattered, write contiguous rows
                for (int i = tid; i < HDIM * KDIM; i += TPB) {
                    int k = i / HDIM, h = i - k * HDIM;
                    s_W2t[k * 48 + h] = wW2[lj * HDIM * KDIM + h * KDIM + k];
                }
                const float4* gsrc = (const float4*)(gW + lj * KDIM * DDIM);
                for (int i = tid; i < KDIM * DDIM / 4; i += TPB)
                    ((float4*)s_gh)[i] = gsrc[i];
                if (j < 2) {
                    if (l == 0) {
                        for (int i = tid; i < NELEC * KDIM; i += TPB)
                            s_hx[(i >> 6) * PAD + (i & 63)] = h0tab[j * KDIM + (i & 63)];
                    } else {
                        const float4* hsrc = (const float4*)(hW + ((l - 1) * 2 + j) * DDIM * KDIM);
                        for (int i = tid; i < DDIM * KDIM / 4; i += TPB)
                            ((float4*)s_weh)[i] = hsrc[i];
                    }
                }
            }
            __syncthreads();

            // ---- hx = elec @ hW (reads hW copy in weh) ----
            if (j < 2 && l > 0) {
                u64 c0 = 0ULL, c1 = 0ULL;
                const float4* er = (const float4*)(s_elec + rr * DDIM);
                for (int d4 = 0; d4 < DDIM / 4; d4++) {
                    float4 ev = er[d4];
                    const ulonglong2* w0 = (const ulonglong2*)(s_weh + (d4 * 4 + 0) * KDIM) + cc;
                    const ulonglong2* w1 = (const ulonglong2*)(s_weh + (d4 * 4 + 1) * KDIM) + cc;
                    const ulonglong2* w2 = (const ulonglong2*)(s_weh + (d4 * 4 + 2) * KDIM) + cc;
                    const ulonglong2* w3 = (const ulonglong2*)(s_weh + (d4 * 4 + 3) * KDIM) + cc;
                    ulonglong2 v0 = *w0, v1 = *w1, v2 = *w2, v3 = *w3;
                    u64 e0 = pack2(ev.x, ev.x), e1 = pack2(ev.y, ev.y);
                    u64 e2 = pack2(ev.z, ev.z), e3 = pack2(ev.w, ev.w);
                    c0 = ffma2(e0, v0.x, c0); c1 = ffma2(e0, v0.y, c1);
                    c0 = ffma2(e1, v1.x, c0); c1 = ffma2(e1, v1.y, c1);
                    c0 = ffma2(e2, v2.x, c0); c1 = ffma2(e2, v2.y, c1);
                    c0 = ffma2(e3, v3.x, c0); c1 = ffma2(e3, v3.y, c1);
                }
                float x0, y0, x1, y1;
                unpack2(c0, x0, y0); unpack2(c1, x1, y1);
                float* dst = s_hx + rr * PAD + cc * 4;
                dst[0] = x0; dst[1] = y0; dst[2] = x1; dst[3] = y1;
                __syncthreads();
            } else if (l > 0) {
                // keep barrier count uniform only when needed; j==2 has no hx step
            }
            if (j < 2 && l > 0) { /* barrier already done above */ }

            // ---- edge MLP (k-split S ways), packed fp32x2 ----
            if (tid < Ej * S) {
                int e = tid % Ej;
                int half = tid / Ej;
                float d = s_d[base + e];
                float env = d * d * __expf(-d);

                u64 hid2[24];
                {
                    const ulonglong2* bv = (const ulonglong2*)s_b1;
#pragma unroll
                    for (int i = 0; i < 12; i++) {
                        ulonglong2 bb = bv[i];
                        hid2[2 * i] = bb.x; hid2[2 * i + 1] = bb.y;
                    }
                }
#pragma unroll 4
                for (int f = 0; f < FDIM; f++) {
                    float t = d - s_mu[f];
                    float fe = env * __expf(-t * t * s_iv[f]);
                    u64 fe2 = pack2(fe, fe);
                    const ulonglong2* w1f = (const ulonglong2*)(s_W1 + f * 48);
#pragma unroll
                    for (int h = 0; h < 12; h++) {
                        ulonglong2 w = w1f[h];
                        hid2[2 * h]     = ffma2(fe2, w.x, hid2[2 * h]);
                        hid2[2 * h + 1] = ffma2(fe2, w.y, hid2[2 * h + 1]);
                    }
                }
#pragma unroll
                for (int i = 0; i < 24; i++) {
                    float x, y; unpack2(hid2[i], x, y);
                    x = __fdividef(x, 1.0f + __expf(-x));
                    y = __fdividef(y, 1.0f + __expf(-y));
                    hid2[i] = pack2(x, y);
                }

                int snd = s_send[base + e];
                const float* hx = ((j < 2) ? s_hx : s_nuc) + snd * PAD + half * Kper;
                float* o = s_weh + e * PAD + half * Kper;
                for (int kk = 0; kk < Kper; kk += 4) {
                    int kbase = half * Kper + kk;
                    const ulonglong2* r0 = (const ulonglong2*)(s_W2t + (kbase + 0) * 48);
                    const ulonglong2* r1 = (const ulonglong2*)(s_W2t + (kbase + 1) * 48);
                    const ulonglong2* r2 = (const ulonglong2*)(s_W2t + (kbase + 2) * 48);
                    const ulonglong2* r3 = (const ulonglong2*)(s_W2t + (kbase + 3) * 48);
                    u64 p0 = 0, p1 = 0, p2 = 0, p3 = 0;
                    u64 q0 = 0, q1 = 0, q2 = 0, q3 = 0;
#pragma unroll
                    for (int h = 0; h < 12; h++) {
                        u64 h0 = hid2[2 * h], h1 = hid2[2 * h + 1];
                        ulonglong2 w0 = r0[h], w1 = r1[h], w2 = r2[h], w3 = r3[h];
                        p0 = ffma2(h0, w0.x, p0); q0 = ffma2(h1, w0.y, q0);
                        p1 = ffma2(h0, w1.x, p1); q1 = ffma2(h1, w1.y, q1);
                        p2 = ffma2(h0, w2.x, p2); q2 = ffma2(h1, w2.y, q2);
                        p3 = ffma2(h0, w3.x, p3); q3 = ffma2(h1, w3.y, q3);
                    }
                    float4 hxv = *(const float4*)(hx + kk);
                    float4 res;
                    float ax_, bx_, cx_, dx_;
                    unpack2(p0, ax_, bx_); unpack2(q0, cx_, dx_);
                    res.x = ((ax_ + bx_) + (cx_ + dx_)) * hxv.x;
                    unpack2(p1, ax_, bx_); unpack2(q1, cx_, dx_);
                    res.y = ((ax_ + bx_) + (cx_ + dx_)) * hxv.y;
                    unpack2(p2, ax_, bx_); unpack2(q2, cx_, dx_);
                    res.z = ((ax_ + bx_) + (cx_ + dx_)) * hxv.z;
                    unpack2(p3, ax_, bx_); unpack2(q3, cx_, dx_);
                    res.w = ((ax_ + bx_) + (cx_ + dx_)) * hxv.w;
                    *(float4*)(o + kk) = res;
                }
            }
            __syncthreads();

            // ---- receiver gather into z (row rr handled by its own half-warp) ----
            {
                int dg = s_deg[j * NELEC + rr];
                const int* er = s_edg + (j * NELEC + rr) * 8;
                u64 g0 = 0ULL, g1 = 0ULL;
                for (int i = 0; i < dg; i++) {
                    const ulonglong2* p = (const ulonglong2*)(s_weh + er[i] * PAD) + cc;
                    ulonglong2 v = *p;
                    g0 = fadd2(g0, v.x); g1 = fadd2(g1, v.y);
                }
                ulonglong2* zp = (ulonglong2*)(s_z + rr * PAD) + cc;
                ulonglong2 zv2; zv2.x = g0; zv2.y = g1;
                *zp = zv2;
            }
            __syncwarp();

            // ---- z @ gW accumulate into registers (across j) ----
            {
                const float4* zr = (const float4*)(s_z + rr * PAD);
#pragma unroll 2
                for (int k4 = 0; k4 < 16; k4++) {
                    float4 z4 = zr[k4];
                    const ulonglong2* row0 = (const ulonglong2*)(s_gh + (k4 * 4 + 0) * DDIM) + cc * 2;
                    const ulonglong2* row1 = (const ulonglong2*)(s_gh + (k4 * 4 + 1) * DDIM) + cc * 2;
                    const ulonglong2* row2 = (const ulonglong2*)(s_gh + (k4 * 4 + 2) * DDIM) + cc * 2;
                    const ulonglong2* row3 = (const ulonglong2*)(s_gh + (k4 * 4 + 3) * DDIM) + cc * 2;
                    u64 z0 = pack2(z4.x, z4.x), z1 = pack2(z4.y, z4.y);
                    u64 z2 = pack2(z4.z, z4.z), z3 = pack2(z4.w, z4.w);
                    ulonglong2 wa, wb;
                    wa = row0[0]; wb = row0[1];
                    a0 = ffma2(z0, wa.x, a0); a1 = ffma2(z0, wa.y, a1);
                    a2 = ffma2(z0, wb.x, a2); a3 = ffma2(z0, wb.y, a3);
                    wa = row1[0]; wb = row1[1];
                    a0 = ffma2(z1, wa.x, a0); a1 = ffma2(z1, wa.y, a1);
                    a2 = ffma2(z1, wb.x, a2); a3 = ffma2(z1, wb.y, a3);
                    wa = row2[0]; wb = row2[1];
                    a0 = ffma2(z2, wa.x, a0); a1 = ffma2(z2, wa.y, a1);
                    a2 = ffma2(z2, wb.x, a2); a3 = ffma2(z2, wb.y, a3);
                    wa = row3[0]; wb = row3[1];
                    a0 = ffma2(z3, wa.x, a0); a1 = ffma2(z3, wa.y, a1);
                    a2 = ffma2(z3, wb.x, a2); a3 = ffma2(z3, wb.y, a3);
                }
            }
            __syncthreads();
        }

        // ---- fold register update into elec ----
        {
            float* dst = s_elec + rr * DDIM + cc * 8;
            float x, y;
            unpack2(a0, x, y); dst[0] += x; dst[1] += y;
            unpack2(a1, x, y); dst[2] += x; dst[3] += y;
            unpack2(a2, x, y); dst[4] += x; dst[5] += y;
            unpack2(a3, x, y); dst[6] += x; dst[7] += y;
        }
        __syncthreads();
    }

    // ---- write result ----
    for (int i = tid; i < NELEC * DDIM / 4; i += TPB)
        ((float4*)(out + b * NELEC * DDIM))[i] = ((const float4*)s_elec)[i];
}

extern "C" void kernel_launch(void* const* d_in, const int* in_sizes, int n_in,
                              void* d_out, int out_size) {
    const float* rs     = (const float*)d_in[0];
    const float* coords = (const float*)d_in[1];
    const float* Xtab   = (const float*)d_in[2];
    const float* Yw     = (const float*)d_in[3];
    const float* wW1    = (const float*)d_in[4];
    const float* wb1    = (const float*)d_in[5];
    const float* wW2    = (const float*)d_in[6];
    const float* h0tab  = (const float*)d_in[7];
    const float* hW     = (const float*)d_in[8];
    const float* gW     = (const float*)d_in[9];
    const int* same_s   = (const int*)d_in[10];
    const int* same_r   = (const int*)d_in[11];
    const int* anti_s   = (const int*)d_in[12];
    const int* anti_r   = (const int*)d_in[13];
    const int* ne_s     = (const int*)d_in[14];
    const int* ne_r     = (const int*)d_in[15];
    float* out = (float*)d_out;

    int B = in_sizes[0] / (NELEC * 3);

    cudaFuncSetAttribute(schnet_kernel,
                         cudaFuncAttributeMaxDynamicSharedMemorySize, SMEM_BYTES);

    csr_kernel<<<1, 32>>>(same_r, anti_r, ne_r);
    schnet_kernel<<<B, TPB, SMEM_BYTES>>>(rs, coords, Xtab, Yw, wW1, wb1, wW2,
                                          h0tab, hW, gW, same_s, same_r,
                                          anti_s, anti_r, ne_s, ne_r, out);
}

// round 7
// speedup vs baseline: 1.9952x; 1.4700x over previous
#include <cuda_runtime.h>

typedef unsigned long long u64;

#define NELEC 16
#define NNUC  4
#define DDIM  128
#define KDIM  64
#define FDIM  32
#define HDIM  45
#define E0    112
#define E1    128
#define E2    64
#define ETOT  304
#define TPB   256
#define PAD   68   // row pad for weh/z/hx/nuc (float4-aligned, conflict-free)

// ---- shared memory layout (float offsets) ----
#define OFF_ELEC 0                  // 2048
#define OFF_HX   2048               // 16*68 = 1088
#define OFF_WEH  3136               // 128*68 = 8704
#define OFF_Z    11840              // 16*68 = 1088
#define OFF_W1   12928              // 32*48 = 1536 (padded rows, pad zeroed)
#define OFF_B1   14464              // 48 (pad zeroed)
#define OFF_W2T  14512              // 64*48 = 3072 (TRANSPOSED, pad zeroed)
#define OFF_GH   17584              // 128*64 = 8192 (gW buffer)
#define OFF_NUC  25776              // 4*68 = 272
#define OFF_D    26048              // 304
#define OFF_SEND 26352              // 304 ints
#define OFF_RS   26656              // 48
#define OFF_CO   26704              // 12
#define OFF_MU   26716              // 32
#define OFF_IV   26748              // 32
#define OFF_DEG  26780              // 48 ints
#define OFF_EDG  26828              // 384 ints
#define SMEM_FLOATS 27212
#define SMEM_BYTES (SMEM_FLOATS * 4)   // 108848 B -> 2 CTAs/SM

__device__ __forceinline__ u64 ffma2(u64 a, u64 b, u64 c) {
    u64 d; asm("fma.rn.f32x2 %0,%1,%2,%3;" : "=l"(d) : "l"(a), "l"(b), "l"(c)); return d;
}
__device__ __forceinline__ u64 fadd2(u64 a, u64 b) {
    u64 d; asm("add.rn.f32x2 %0,%1,%2;" : "=l"(d) : "l"(a), "l"(b)); return d;
}
__device__ __forceinline__ u64 pack2(float x, float y) {
    u64 r; asm("mov.b64 %0,{%1,%2};" : "=l"(r) : "f"(x), "f"(y)); return r;
}
__device__ __forceinline__ void unpack2(u64 v, float& x, float& y) {
    asm("mov.b64 {%0,%1},%2;" : "=f"(x), "=f"(y) : "l"(v));
}

// receiver CSR (LOCAL per-j edge indices), rebuilt every launch
__device__ int g_deg[3][NELEC];
__device__ int g_edge[3][NELEC][8];

__global__ void csr_kernel(const int* __restrict__ same_r,
                           const int* __restrict__ anti_r,
                           const int* __restrict__ ne_r) {
    if (blockIdx.x == 0 && threadIdx.x == 0) {
        for (int j = 0; j < 3; j++)
            for (int r = 0; r < NELEC; r++) g_deg[j][r] = 0;
        for (int e = 0; e < E0; e++) {
            int r = same_r[e]; int c = g_deg[0][r];
            if (c < 8) g_edge[0][r][c] = e;
            g_deg[0][r] = c + 1;
        }
        for (int e = 0; e < E1; e++) {
            int r = anti_r[e]; int c = g_deg[1][r];
            if (c < 8) g_edge[1][r][c] = e;
            g_deg[1][r] = c + 1;
        }
        for (int e = 0; e < E2; e++) {
            int r = ne_r[e]; int c = g_deg[2][r];
            if (c < 8) g_edge[2][r][c] = e;
            g_deg[2][r] = c + 1;
        }
    }
}

__global__ __launch_bounds__(TPB, 2)
void schnet_kernel(const float* __restrict__ rs, const float* __restrict__ coords,
                   const float* __restrict__ Xtab, const float* __restrict__ Yw,
                   const float* __restrict__ wW1, const float* __restrict__ wb1,
                   const float* __restrict__ wW2, const float* __restrict__ h0tab,
                   const float* __restrict__ hW, const float* __restrict__ gW,
                   const int* __restrict__ same_s, const int* __restrict__ same_r,
                   const int* __restrict__ anti_s, const int* __restrict__ anti_r,
                   const int* __restrict__ ne_s, const int* __restrict__ ne_r,
                   float* __restrict__ out) {
    extern __shared__ float sm[];
    const int tid = threadIdx.x;
    const int b = blockIdx.x;

    float* s_elec = sm + OFF_ELEC;
    float* s_hx   = sm + OFF_HX;
    float* s_weh  = sm + OFF_WEH;
    float* s_z    = sm + OFF_Z;
    float* s_W1   = sm + OFF_W1;
    float* s_b1   = sm + OFF_B1;
    float* s_W2t  = sm + OFF_W2T;
    float* s_gh   = sm + OFF_GH;
    float* s_nuc  = sm + OFF_NUC;
    float* s_d    = sm + OFF_D;
    int*   s_send = (int*)(sm + OFF_SEND);
    float* s_rs   = sm + OFF_RS;
    float* s_co   = sm + OFF_CO;
    float* s_mu   = sm + OFF_MU;
    float* s_iv   = sm + OFF_IV;
    int*   s_deg  = (int*)(sm + OFF_DEG);
    int*   s_edg  = (int*)(sm + OFF_EDG);

    // ---- block init ----
    for (int i = tid; i < NELEC * 3; i += TPB) s_rs[i] = rs[b * NELEC * 3 + i];
    for (int i = tid; i < NNUC * 3; i += TPB) s_co[i] = coords[i];
    for (int i = tid; i < NELEC * DDIM; i += TPB) s_elec[i] = Xtab[i & (DDIM - 1)];
    for (int i = tid; i < NNUC * KDIM; i += TPB)
        s_nuc[(i >> 6) * PAD + (i & 63)] = Yw[i];
    for (int i = tid; i < E0; i += TPB) s_send[i] = same_s[i];
    for (int i = tid; i < E1; i += TPB) s_send[E0 + i] = anti_s[i];
    for (int i = tid; i < E2; i += TPB) s_send[E0 + E1 + i] = ne_s[i];
    if (tid < FDIM) {
        float q = tid * (1.0f / 31.0f);
        float mu = 10.0f * q * q;
        float sg = (1.0f + 10.0f * q) * (1.0f / 7.0f);
        s_mu[tid] = mu;
        s_iv[tid] = 1.0f / (sg * sg);
    }
    for (int i = tid; i < 3 * NELEC; i += TPB) s_deg[i] = ((const int*)g_deg)[i];
    for (int i = tid; i < 3 * NELEC * 8; i += TPB) s_edg[i] = ((const int*)g_edge)[i];
    // zero pad lanes of W1/W2t/b1 once (staging never writes h>=45)
    for (int i = tid; i < FDIM; i += TPB) {
        s_W1[i * 48 + 45] = 0.f; s_W1[i * 48 + 46] = 0.f; s_W1[i * 48 + 47] = 0.f;
    }
    for (int i = tid; i < KDIM; i += TPB) {
        s_W2t[i * 48 + 45] = 0.f; s_W2t[i * 48 + 46] = 0.f; s_W2t[i * 48 + 47] = 0.f;
    }
    if (tid < 3) s_b1[45 + tid] = 0.f;
    __syncthreads();

    // ---- edge distances ----
    for (int e = tid; e < ETOT; e += TPB) {
        int s = s_send[e];
        float ax, ay, az, bx, by, bz;
        if (e < E0 + E1) {
            int r = (e < E0) ? same_r[e] : anti_r[e - E0];
            ax = s_rs[s * 3 + 0]; ay = s_rs[s * 3 + 1]; az = s_rs[s * 3 + 2];
            bx = s_rs[r * 3 + 0]; by = s_rs[r * 3 + 1]; bz = s_rs[r * 3 + 2];
        } else {
            int r = ne_r[e - E0 - E1];
            ax = s_co[s * 3 + 0]; ay = s_co[s * 3 + 1]; az = s_co[s * 3 + 2];
            bx = s_rs[r * 3 + 0]; by = s_rs[r * 3 + 1]; bz = s_rs[r * 3 + 2];
        }
        float dx = ax - bx, dy = ay - by, dz = az - bz;
        s_d[e] = sqrtf(dx * dx + dy * dy + dz * dz);
    }
    __syncthreads();

    const int rp  = tid >> 5;       // 0..7 (warp id): handles rows rp and rp+8
    const int c2  = tid & 31;       // 0..31 lane
    const int gr  = (tid >> 5) + ((tid >> 4) & 1) * 8;  // gather row (warp-matched)
    const int gcc = tid & 15;                           // gather k-group

    // ================= layer loop =================
    for (int l = 0; l < 3; l++) {
        // persistent update accumulators: rows rp/rp+8, cols c2*4..+3
        u64 a0 = 0ULL, a1 = 0ULL, a2 = 0ULL, a3 = 0ULL;

        for (int j = 0; j < 3; j++) {
            int Ej, base;
            if (j == 0)      { Ej = E0; base = 0;       }
            else if (j == 1) { Ej = E1; base = E0;      }
            else             { Ej = E2; base = E0 + E1; }

            // ---- stage all weights for this (l,j); hW goes into weh (free now) ----
            {
                int lj = l * 3 + j;
                for (int i = tid; i < FDIM * HDIM; i += TPB) {
                    int f = i / HDIM, h = i - f * HDIM;
                    s_W1[f * 48 + h] = wW1[lj * FDIM * HDIM + i];
                }
                if (tid < HDIM) s_b1[tid] = wb1[lj * HDIM + tid];
                // transposed W2: read wW2[h][k] scattered, write contiguous rows
                for (int i = tid; i < HDIM * KDIM; i += TPB) {
                    int k = i / HDIM, h = i - k * HDIM;
                    s_W2t[k * 48 + h] = wW2[lj * HDIM * KDIM + h * KDIM + k];
                }
                const float4* gsrc = (const float4*)(gW + lj * KDIM * DDIM);
                for (int i = tid; i < KDIM * DDIM / 4; i += TPB)
                    ((float4*)s_gh)[i] = gsrc[i];
                if (j < 2) {
                    if (l == 0) {
                        for (int i = tid; i < NELEC * KDIM; i += TPB)
                            s_hx[(i >> 6) * PAD + (i & 63)] = h0tab[j * KDIM + (i & 63)];
                    } else {
                        const float4* hsrc = (const float4*)(hW + ((l - 1) * 2 + j) * DDIM * KDIM);
                        for (int i = tid; i < DDIM * KDIM / 4; i += TPB)
                            ((float4*)s_weh)[i] = hsrc[i];
                    }
                }
            }
            __syncthreads();

            // ---- hx = elec @ hW : 2 rows per thread, k-pair per lane ----
            if (j < 2 && l > 0) {
                u64 acc0 = 0ULL, acc1 = 0ULL;   // rows rp, rp+8; k = c2*2, c2*2+1
                const float4* e0v = (const float4*)(s_elec + rp * DDIM);
                const float4* e1v = (const float4*)(s_elec + (rp + 8) * DDIM);
                for (int d4 = 0; d4 < DDIM / 4; d4++) {
                    float4 va = e0v[d4], vb = e1v[d4];
                    u64 w0 = ((const u64*)(s_weh + (d4 * 4 + 0) * KDIM))[c2];
                    u64 w1 = ((const u64*)(s_weh + (d4 * 4 + 1) * KDIM))[c2];
                    u64 w2 = ((const u64*)(s_weh + (d4 * 4 + 2) * KDIM))[c2];
                    u64 w3 = ((const u64*)(s_weh + (d4 * 4 + 3) * KDIM))[c2];
                    acc0 = ffma2(pack2(va.x, va.x), w0, acc0);
                    acc1 = ffma2(pack2(vb.x, vb.x), w0, acc1);
                    acc0 = ffma2(pack2(va.y, va.y), w1, acc0);
                    acc1 = ffma2(pack2(vb.y, vb.y), w1, acc1);
                    acc0 = ffma2(pack2(va.z, va.z), w2, acc0);
                    acc1 = ffma2(pack2(vb.z, vb.z), w2, acc1);
                    acc0 = ffma2(pack2(va.w, va.w), w3, acc0);
                    acc1 = ffma2(pack2(vb.w, vb.w), w3, acc1);
                }
                ((u64*)(s_hx + rp * PAD))[c2] = acc0;
                ((u64*)(s_hx + (rp + 8) * PAD))[c2] = acc1;
                __syncthreads();
            }

            // ---- edge MLP: one thread per edge, full 64-k output ----
            if (tid < Ej) {
                float d = s_d[base + tid];
                float env = d * d * __expf(-d);

                u64 hid2[24];
                {
                    const ulonglong2* bv = (const ulonglong2*)s_b1;
#pragma unroll
                    for (int i = 0; i < 12; i++) {
                        ulonglong2 bb = bv[i];
                        hid2[2 * i] = bb.x; hid2[2 * i + 1] = bb.y;
                    }
                }
#pragma unroll 4
                for (int f = 0; f < FDIM; f++) {
                    float t = d - s_mu[f];
                    float fe = env * __expf(-t * t * s_iv[f]);
                    u64 fe2 = pack2(fe, fe);
                    const ulonglong2* w1f = (const ulonglong2*)(s_W1 + f * 48);
#pragma unroll
                    for (int h = 0; h < 12; h++) {
                        ulonglong2 w = w1f[h];
                        hid2[2 * h]     = ffma2(fe2, w.x, hid2[2 * h]);
                        hid2[2 * h + 1] = ffma2(fe2, w.y, hid2[2 * h + 1]);
                    }
                }
#pragma unroll
                for (int i = 0; i < 24; i++) {
                    float x, y; unpack2(hid2[i], x, y);
                    x = __fdividef(x, 1.0f + __expf(-x));
                    y = __fdividef(y, 1.0f + __expf(-y));
                    hid2[i] = pack2(x, y);
                }

                int snd = s_send[base + tid];
                const float* hx = ((j < 2) ? s_hx : s_nuc) + snd * PAD;
                float* o = s_weh + tid * PAD;
                for (int kk = 0; kk < KDIM; kk += 4) {
                    const ulonglong2* r0 = (const ulonglong2*)(s_W2t + (kk + 0) * 48);
                    const ulonglong2* r1 = (const ulonglong2*)(s_W2t + (kk + 1) * 48);
                    const ulonglong2* r2 = (const ulonglong2*)(s_W2t + (kk + 2) * 48);
                    const ulonglong2* r3 = (const ulonglong2*)(s_W2t + (kk + 3) * 48);
                    u64 p0 = 0, p1 = 0, p2 = 0, p3 = 0;
                    u64 q0 = 0, q1 = 0, q2 = 0, q3 = 0;
#pragma unroll
                    for (int h = 0; h < 12; h++) {
                        u64 h0 = hid2[2 * h], h1 = hid2[2 * h + 1];
                        ulonglong2 w0 = r0[h], w1 = r1[h], w2 = r2[h], w3 = r3[h];
                        p0 = ffma2(h0, w0.x, p0); q0 = ffma2(h1, w0.y, q0);
                        p1 = ffma2(h0, w1.x, p1); q1 = ffma2(h1, w1.y, q1);
                        p2 = ffma2(h0, w2.x, p2); q2 = ffma2(h1, w2.y, q2);
                        p3 = ffma2(h0, w3.x, p3); q3 = ffma2(h1, w3.y, q3);
                    }
                    float4 hxv = *(const float4*)(hx + kk);
                    float4 res;
                    float ax_, bx_, cx_, dx_;
                    unpack2(p0, ax_, bx_); unpack2(q0, cx_, dx_);
                    res.x = ((ax_ + bx_) + (cx_ + dx_)) * hxv.x;
                    unpack2(p1, ax_, bx_); unpack2(q1, cx_, dx_);
                    res.y = ((ax_ + bx_) + (cx_ + dx_)) * hxv.y;
                    unpack2(p2, ax_, bx_); unpack2(q2, cx_, dx_);
                    res.z = ((ax_ + bx_) + (cx_ + dx_)) * hxv.z;
                    unpack2(p3, ax_, bx_); unpack2(q3, cx_, dx_);
                    res.w = ((ax_ + bx_) + (cx_ + dx_)) * hxv.w;
                    *(float4*)(o + kk) = res;
                }
            }
            __syncthreads();

            // ---- receiver gather into z (warp produces the rows it consumes) ----
            {
                int dg = s_deg[j * NELEC + gr];
                const int* er = s_edg + (j * NELEC + gr) * 8;
                u64 g0 = 0ULL, g1 = 0ULL;
                for (int i = 0; i < dg; i++) {
                    const ulonglong2* p = (const ulonglong2*)(s_weh + er[i] * PAD) + gcc;
                    ulonglong2 v = *p;
                    g0 = fadd2(g0, v.x); g1 = fadd2(g1, v.y);
                }
                ulonglong2* zp = (ulonglong2*)(s_z + gr * PAD) + gcc;
                ulonglong2 zv2; zv2.x = g0; zv2.y = g1;
                *zp = zv2;
            }
            __syncwarp();

            // ---- z @ gW : 2 rows per thread, 4 cols, full k ----
            {
                const float4* z0 = (const float4*)(s_z + rp * PAD);
                const float4* z1 = (const float4*)(s_z + (rp + 8) * PAD);
#pragma unroll 2
                for (int k4 = 0; k4 < 16; k4++) {
                    float4 za = z0[k4], zb = z1[k4];
                    ulonglong2 w;
                    u64 zka, zkb;
                    w = ((const ulonglong2*)(s_gh + (k4 * 4 + 0) * DDIM))[c2];
                    zka = pack2(za.x, za.x); zkb = pack2(zb.x, zb.x);
                    a0 = ffma2(zka, w.x, a0); a1 = ffma2(zka, w.y, a1);
                    a2 = ffma2(zkb, w.x, a2); a3 = ffma2(zkb, w.y, a3);
                    w = ((const ulonglong2*)(s_gh + (k4 * 4 + 1) * DDIM))[c2];
                    zka = pack2(za.y, za.y); zkb = pack2(zb.y, zb.y);
                    a0 = ffma2(zka, w.x, a0); a1 = ffma2(zka, w.y, a1);
                    a2 = ffma2(zkb, w.x, a2); a3 = ffma2(zkb, w.y, a3);
                    w = ((const ulonglong2*)(s_gh + (k4 * 4 + 2) * DDIM))[c2];
                    zka = pack2(za.z, za.z); zkb = pack2(zb.z, zb.z);
                    a0 = ffma2(zka, w.x, a0); a1 = ffma2(zka, w.y, a1);
                    a2 = ffma2(zkb, w.x, a2); a3 = ffma2(zkb, w.y, a3);
                    w = ((const ulonglong2*)(s_gh + (k4 * 4 + 3) * DDIM))[c2];
                    zka = pack2(za.w, za.w); zkb = pack2(zb.w, zb.w);
                    a0 = ffma2(zka, w.x, a0); a1 = ffma2(zka, w.y, a1);
                    a2 = ffma2(zkb, w.x, a2); a3 = ffma2(zkb, w.y, a3);
                }
            }
            __syncthreads();
        }

        // ---- fold register update into elec ----
        {
            float* dst0 = s_elec + rp * DDIM + c2 * 4;
            float* dst1 = s_elec + (rp + 8) * DDIM + c2 * 4;
            float x, y;
            unpack2(a0, x, y); dst0[0] += x; dst0[1] += y;
            unpack2(a1, x, y); dst0[2] += x; dst0[3] += y;
            unpack2(a2, x, y); dst1[0] += x; dst1[1] += y;
            unpack2(a3, x, y); dst1[2] += x; dst1[3] += y;
        }
        __syncthreads();
    }

    // ---- write result ----
    for (int i = tid; i < NELEC * DDIM / 4; i += TPB)
        ((float4*)(out + b * NELEC * DDIM))[i] = ((const float4*)s_elec)[i];
}

extern "C" void kernel_launch(void* const* d_in, const int* in_sizes, int n_in,
                              void* d_out, int out_size) {
    const float* rs     = (const float*)d_in[0];
    const float* coords = (const float*)d_in[1];
    const float* Xtab   = (const float*)d_in[2];
    const float* Yw     = (const float*)d_in[3];
    const float* wW1    = (const float*)d_in[4];
    const float* wb1    = (const float*)d_in[5];
    const float* wW2    = (const float*)d_in[6];
    const float* h0tab  = (const float*)d_in[7];
    const float* hW     = (const float*)d_in[8];
    const float* gW     = (const float*)d_in[9];
    const int* same_s   = (const int*)d_in[10];
    const int* same_r   = (const int*)d_in[11];
    const int* anti_s   = (const int*)d_in[12];
    const int* anti_r   = (const int*)d_in[13];
    const int* ne_s     = (const int*)d_in[14];
    const int* ne_r     = (const int*)d_in[15];
    float* out = (float*)d_out;

    int B = in_sizes[0] / (NELEC * 3);

    cudaFuncSetAttribute(schnet_kernel,
                         cudaFuncAttributeMaxDynamicSharedMemorySize, SMEM_BYTES);

    csr_kernel<<<1, 32>>>(same_r, anti_r, ne_r);
    schnet_kernel<<<B, TPB, SMEM_BYTES>>>(rs, coords, Xtab, Yw, wW1, wb1, wW2,
                                          h0tab, hW, gW, same_s, same_r,
                                          anti_s, anti_r, ne_s, ne_r, out);
}

// round 8
// speedup vs baseline: 3.4788x; 1.7436x over previous
#include <cuda_runtime.h>

typedef unsigned long long u64;

#define NELEC 16
#define NNUC  4
#define DDIM  128
#define KDIM  64
#define FDIM  32
#define HDIM  45
#define E0    112
#define E1    128
#define E2    64
#define ETOT  304
#define TPB   256
#define PAD   68
#define TGRID 16384
#define TMAX  20.0f

// ---- shared memory layout (float offsets) ----
#define OFF_ELEC 0          // 2048
#define OFF_HX0  2048       // 16*68 = 1088
#define OFF_HX1  3136       // 16*68 = 1088
#define OFF_WEH  4224       // 128*68 = 8704 (also hW0 stage buffer)
#define OFF_Z    12928      // 16*68 = 1088
#define OFF_GH   14016      // 128*64 = 8192 (gW / hW1 stage buffer)
#define OFF_NUC  22208      // 4*68 = 272
#define OFF_D    22480      // 304
#define OFF_SEND 22784      // 304 ints
#define OFF_RS   23088      // 48
#define OFF_CO   23136      // 12
#define OFF_DEG  23148      // 48 ints
#define OFF_EDG  23196      // 384 ints
#define SMEM_FLOATS 23580
#define SMEM_BYTES (SMEM_FLOATS * 4)    // 94320 B -> 2 CTAs/SM

__device__ __forceinline__ u64 ffma2(u64 a, u64 b, u64 c) {
    u64 d; asm("fma.rn.f32x2 %0,%1,%2,%3;" : "=l"(d) : "l"(a), "l"(b), "l"(c)); return d;
}
__device__ __forceinline__ u64 pack2(float x, float y) {
    u64 r; asm("mov.b64 %0,{%1,%2};" : "=l"(r) : "f"(x), "f"(y)); return r;
}
__device__ __forceinline__ void unpack2(u64 v, float& x, float& y) {
    asm("mov.b64 {%0,%1},%2;" : "=f"(x), "=f"(y) : "l"(v));
}

// per-launch precomputed MLP table: we[lj][grid][k]
__device__ float g_tab[9ULL * TGRID * KDIM];   // 37.75 MB

// receiver CSR (LOCAL per-j edge indices), rebuilt every launch
__device__ int g_deg[3][NELEC];
__device__ int g_edge[3][NELEC][8];

__global__ void csr_kernel(const int* __restrict__ same_r,
                           const int* __restrict__ anti_r,
                           const int* __restrict__ ne_r) {
    if (blockIdx.x == 0 && threadIdx.x == 0) {
        for (int j = 0; j < 3; j++)
            for (int r = 0; r < NELEC; r++) g_deg[j][r] = 0;
        for (int e = 0; e < E0; e++) {
            int r = same_r[e]; int c = g_deg[0][r];
            if (c < 8) g_edge[0][r][c] = e;
            g_deg[0][r] = c + 1;
        }
        for (int e = 0; e < E1; e++) {
            int r = anti_r[e]; int c = g_deg[1][r];
            if (c < 8) g_edge[1][r][c] = e;
            g_deg[1][r] = c + 1;
        }
        for (int e = 0; e < E2; e++) {
            int r = ne_r[e]; int c = g_deg[2][r];
            if (c < 8) g_edge[2][r][c] = e;
            g_deg[2][r] = c + 1;
        }
    }
}

// ---- table precompute: we[k](d) on a uniform grid, per (l,j) ----
// dyn smem: W1 1440 | b1 48 | W2t 64*45=2880 | tile 256*68=17408  -> 21776 floats
#define TK_SMEM_FLOATS 21776
__global__ void table_kernel(const float* __restrict__ wW1,
                             const float* __restrict__ wb1,
                             const float* __restrict__ wW2) {
    extern __shared__ float ts[];
    float* sW1  = ts;            // [32][45]
    float* sb1  = ts + 1440;     // [45]
    float* sW2t = ts + 1488;     // [64][45]
    float* tile = ts + 4368;     // [256][68]
    int lj = blockIdx.x;
    int tid = threadIdx.x;
    for (int i = tid; i < FDIM * HDIM; i += 256) sW1[i] = wW1[lj * FDIM * HDIM + i];
    if (tid < HDIM) sb1[tid] = wb1[lj * HDIM + tid];
    for (int i = tid; i < HDIM * KDIM; i += 256) {
        int k = i / HDIM, h = i - k * HDIM;
        sW2t[k * HDIM + h] = wW2[lj * HDIM * KDIM + h * KDIM + k];
    }
    __syncthreads();

    int p = blockIdx.y * 256 + tid;
    float d = p * (TMAX / (float)(TGRID - 1));
    float env = d * d * __expf(-d);
    float hid[HDIM];
#pragma unroll
    for (int h = 0; h < HDIM; h++) hid[h] = sb1[h];
    for (int f = 0; f < FDIM; f++) {
        float q = f * (1.0f / 31.0f);
        float mu = 10.0f * q * q;
        float sg = (1.0f + 10.0f * q) * (1.0f / 7.0f);
        float t = d - mu;
        float fe = env * __expf(-t * t / (sg * sg));
        const float* w1f = sW1 + f * HDIM;
#pragma unroll
        for (int h = 0; h < HDIM; h++) hid[h] += fe * w1f[h];
    }
#pragma unroll
    for (int h = 0; h < HDIM; h++) {
        float x = hid[h];
        hid[h] = x / (1.0f + __expf(-x));
    }
    for (int k = 0; k < KDIM; k++) {
        const float* w2 = sW2t + k * HDIM;
        float acc = 0.f;
#pragma unroll
        for (int h = 0; h < HDIM; h++) acc += hid[h] * w2[h];
        tile[tid * PAD + k] = acc;
    }
    __syncthreads();
    // coalesced write-out
    float4* dst = (float4*)(g_tab + ((size_t)lj * TGRID + blockIdx.y * 256) * KDIM);
    for (int i = tid; i < 256 * 16; i += 256) {
        int pl = i >> 4, k4 = i & 15;
        dst[pl * 16 + k4] = *(const float4*)(tile + pl * PAD + k4 * 4);
    }
}

__global__ __launch_bounds__(TPB, 2)
void schnet_kernel(const float* __restrict__ rs, const float* __restrict__ coords,
                   const float* __restrict__ Xtab, const float* __restrict__ Yw,
                   const float* __restrict__ h0tab, const float* __restrict__ hW,
                   const float* __restrict__ gW,
                   const int* __restrict__ same_s, const int* __restrict__ same_r,
                   const int* __restrict__ anti_s, const int* __restrict__ anti_r,
                   const int* __restrict__ ne_s, const int* __restrict__ ne_r,
                   float* __restrict__ out) {
    extern __shared__ float sm[];
    const int tid = threadIdx.x;
    const int b = blockIdx.x;

    float* s_elec = sm + OFF_ELEC;
    float* s_hx0  = sm + OFF_HX0;
    float* s_hx1  = sm + OFF_HX1;
    float* s_weh  = sm + OFF_WEH;
    float* s_z    = sm + OFF_Z;
    float* s_gh   = sm + OFF_GH;
    float* s_nuc  = sm + OFF_NUC;
    float* s_d    = sm + OFF_D;
    int*   s_send = (int*)(sm + OFF_SEND);
    float* s_rs   = sm + OFF_RS;
    float* s_co   = sm + OFF_CO;
    int*   s_deg  = (int*)(sm + OFF_DEG);
    int*   s_edg  = (int*)(sm + OFF_EDG);

    // ---- block init ----
    for (int i = tid; i < NELEC * 3; i += TPB) s_rs[i] = rs[b * NELEC * 3 + i];
    for (int i = tid; i < NNUC * 3; i += TPB) s_co[i] = coords[i];
    for (int i = tid; i < NELEC * DDIM; i += TPB) s_elec[i] = Xtab[i & (DDIM - 1)];
    for (int i = tid; i < NNUC * KDIM; i += TPB)
        s_nuc[(i >> 6) * PAD + (i & 63)] = Yw[i];
    for (int i = tid; i < E0; i += TPB) s_send[i] = same_s[i];
    for (int i = tid; i < E1; i += TPB) s_send[E0 + i] = anti_s[i];
    for (int i = tid; i < E2; i += TPB) s_send[E0 + E1 + i] = ne_s[i];
    for (int i = tid; i < 3 * NELEC; i += TPB) s_deg[i] = ((const int*)g_deg)[i];
    for (int i = tid; i < 3 * NELEC * 8; i += TPB) s_edg[i] = ((const int*)g_edge)[i];
    __syncthreads();

    // ---- edge distances ----
    for (int e = tid; e < ETOT; e += TPB) {
        int s = s_send[e];
        float ax, ay, az, bx, by, bz;
        if (e < E0 + E1) {
            int r = (e < E0) ? same_r[e] : anti_r[e - E0];
            ax = s_rs[s * 3 + 0]; ay = s_rs[s * 3 + 1]; az = s_rs[s * 3 + 2];
            bx = s_rs[r * 3 + 0]; by = s_rs[r * 3 + 1]; bz = s_rs[r * 3 + 2];
        } else {
            int r = ne_r[e - E0 - E1];
            ax = s_co[s * 3 + 0]; ay = s_co[s * 3 + 1]; az = s_co[s * 3 + 2];
            bx = s_rs[r * 3 + 0]; by = s_rs[r * 3 + 1]; bz = s_rs[r * 3 + 2];
        }
        float dx = ax - bx, dy = ay - by, dz = az - bz;
        s_d[e] = sqrtf(dx * dx + dy * dy + dz * dz);
    }
    __syncthreads();

    const int wid  = tid >> 5;
    const int c2   = tid & 31;
    const int rowb = (wid & 3) * 4;       // 4-row block
    const int half = (wid >> 2) * 64;     // column half for z@gW
    const int rr   = tid >> 4;            // gather row
    const int cc   = tid & 15;            // gather k-group

    // ================= layer loop =================
    for (int l = 0; l < 3; l++) {
        // ---- hx phase (both j=0,1 at once) ----
        if (l == 0) {
            for (int i = tid; i < NELEC * KDIM; i += TPB) {
                int r = i >> 6, k = i & 63;
                s_hx0[r * PAD + k] = h0tab[k];
                s_hx1[r * PAD + k] = h0tab[KDIM + k];
            }
            __syncthreads();
        } else {
            const float4* h0src = (const float4*)(hW + (size_t)((l - 1) * 2 + 0) * DDIM * KDIM);
            const float4* h1src = (const float4*)(hW + (size_t)((l - 1) * 2 + 1) * DDIM * KDIM);
            for (int i = tid; i < DDIM * KDIM / 4; i += TPB) {
                ((float4*)s_weh)[i] = h0src[i];
                ((float4*)s_gh)[i]  = h1src[i];
            }
            __syncthreads();
            {
                const float* hWs  = (wid >> 2) ? s_gh : s_weh;
                float* dsthx      = (wid >> 2) ? s_hx1 : s_hx0;
                u64 h0 = 0, h1 = 0, h2 = 0, h3 = 0;
                const float4* e0 = (const float4*)(s_elec + (rowb + 0) * DDIM);
                const float4* e1 = (const float4*)(s_elec + (rowb + 1) * DDIM);
                const float4* e2 = (const float4*)(s_elec + (rowb + 2) * DDIM);
                const float4* e3 = (const float4*)(s_elec + (rowb + 3) * DDIM);
                for (int d4 = 0; d4 < DDIM / 4; d4++) {
                    float4 va = e0[d4], vb = e1[d4], vc = e2[d4], vd = e3[d4];
                    u64 w0 = *(const u64*)(hWs + (d4 * 4 + 0) * KDIM + c2 * 2);
                    u64 w1 = *(const u64*)(hWs + (d4 * 4 + 1) * KDIM + c2 * 2);
                    u64 w2 = *(const u64*)(hWs + (d4 * 4 + 2) * KDIM + c2 * 2);
                    u64 w3 = *(const u64*)(hWs + (d4 * 4 + 3) * KDIM + c2 * 2);
                    h0 = ffma2(pack2(va.x, va.x), w0, h0);
                    h1 = ffma2(pack2(vb.x, vb.x), w0, h1);
                    h2 = ffma2(pack2(vc.x, vc.x), w0, h2);
                    h3 = ffma2(pack2(vd.x, vd.x), w0, h3);
                    h0 = ffma2(pack2(va.y, va.y), w1, h0);
                    h1 = ffma2(pack2(vb.y, vb.y), w1, h1);
                    h2 = ffma2(pack2(vc.y, vc.y), w1, h2);
                    h3 = ffma2(pack2(vd.y, vd.y), w1, h3);
                    h0 = ffma2(pack2(va.z, va.z), w2, h0);
                    h1 = ffma2(pack2(vb.z, vb.z), w2, h1);
                    h2 = ffma2(pack2(vc.z, vc.z), w2, h2);
                    h3 = ffma2(pack2(vd.z, vd.z), w2, h3);
                    h0 = ffma2(pack2(va.w, va.w), w3, h0);
                    h1 = ffma2(pack2(vb.w, vb.w), w3, h1);
                    h2 = ffma2(pack2(vc.w, vc.w), w3, h2);
                    h3 = ffma2(pack2(vd.w, vd.w), w3, h3);
                }
                *(u64*)(dsthx + (rowb + 0) * PAD + c2 * 2) = h0;
                *(u64*)(dsthx + (rowb + 1) * PAD + c2 * 2) = h1;
                *(u64*)(dsthx + (rowb + 2) * PAD + c2 * 2) = h2;
                *(u64*)(dsthx + (rowb + 3) * PAD + c2 * 2) = h3;
            }
            __syncthreads();
        }

        // persistent update accumulators across j
        u64 a0 = 0ULL, a1 = 0ULL, a2 = 0ULL, a3 = 0ULL;

        for (int j = 0; j < 3; j++) {
            int Ej, base;
            if (j == 0)      { Ej = E0; base = 0;       }
            else if (j == 1) { Ej = E1; base = E0;      }
            else             { Ej = E2; base = E0 + E1; }

            // ---- edge MLP (table lerp) || gW staging by idle threads ----
            if (tid < Ej) {
                float d = s_d[base + tid];
                float f = fminf(d, TMAX) * ((float)(TGRID - 1) / TMAX);
                int ii = (int)f;
                if (ii > TGRID - 2) ii = TGRID - 2;
                float fr = f - (float)ii;
                const float4* t0 = (const float4*)(g_tab + ((size_t)(l * 3 + j) * TGRID + ii) * KDIM);
                int snd = s_send[base + tid];
                const float* hx = ((j == 0) ? s_hx0 : (j == 1) ? s_hx1 : s_nuc) + snd * PAD;
                float* o = s_weh + tid * PAD;
#pragma unroll
                for (int k4 = 0; k4 < 16; k4++) {
                    float4 ta = __ldg(t0 + k4);
                    float4 tb = __ldg(t0 + 16 + k4);
                    float4 h4 = *(const float4*)(hx + k4 * 4);
                    float4 r;
                    r.x = fmaf(fr, tb.x - ta.x, ta.x) * h4.x;
                    r.y = fmaf(fr, tb.y - ta.y, ta.y) * h4.y;
                    r.z = fmaf(fr, tb.z - ta.z, ta.z) * h4.z;
                    r.w = fmaf(fr, tb.w - ta.w, ta.w) * h4.w;
                    *(float4*)(o + k4 * 4) = r;
                }
            } else {
                const float4* gsrc = (const float4*)(gW + (size_t)(l * 3 + j) * KDIM * DDIM);
                for (int i = tid - Ej; i < KDIM * DDIM / 4; i += TPB - Ej)
                    ((float4*)s_gh)[i] = gsrc[i];
            }
            __syncthreads();

            // ---- receiver gather into z ----
            {
                int dg = s_deg[j * NELEC + rr];
                const int* er = s_edg + (j * NELEC + rr) * 8;
                float4 acc = make_float4(0.f, 0.f, 0.f, 0.f);
                for (int i = 0; i < dg; i++) {
                    float4 v = *(const float4*)(s_weh + er[i] * PAD + cc * 4);
                    acc.x += v.x; acc.y += v.y; acc.z += v.z; acc.w += v.w;
                }
                *(float4*)(s_z + rr * PAD + cc * 4) = acc;
            }
            __syncthreads();

            // ---- z @ gW : 4 rows per warp, 64-col half, u64 lanes ----
            {
                const float4* z0 = (const float4*)(s_z + (rowb + 0) * PAD);
                const float4* z1 = (const float4*)(s_z + (rowb + 1) * PAD);
                const float4* z2 = (const float4*)(s_z + (rowb + 2) * PAD);
                const float4* z3 = (const float4*)(s_z + (rowb + 3) * PAD);
#pragma unroll 2
                for (int k4 = 0; k4 < 16; k4++) {
                    float4 za = z0[k4], zb = z1[k4], zc = z2[k4], zd = z3[k4];
                    u64 w;
                    w = *(const u64*)(s_gh + (k4 * 4 + 0) * DDIM + half + c2 * 2);
                    a0 = ffma2(pack2(za.x, za.x), w, a0);
                    a1 = ffma2(pack2(zb.x, zb.x), w, a1);
                    a2 = ffma2(pack2(zc.x, zc.x), w, a2);
                    a3 = ffma2(pack2(zd.x, zd.x), w, a3);
                    w = *(const u64*)(s_gh + (k4 * 4 + 1) * DDIM + half + c2 * 2);
                    a0 = ffma2(pack2(za.y, za.y), w, a0);
                    a1 = ffma2(pack2(zb.y, zb.y), w, a1);
                    a2 = ffma2(pack2(zc.y, zc.y), w, a2);
                    a3 = ffma2(pack2(zd.y, zd.y), w, a3);
                    w = *(const u64*)(s_gh + (k4 * 4 + 2) * DDIM + half + c2 * 2);
                    a0 = ffma2(pack2(za.z, za.z), w, a0);
                    a1 = ffma2(pack2(zb.z, zb.z), w, a1);
                    a2 = ffma2(pack2(zc.z, zc.z), w, a2);
                    a3 = ffma2(pack2(zd.z, zd.z), w, a3);
                    w = *(const u64*)(s_gh + (k4 * 4 + 3) * DDIM + half + c2 * 2);
                    a0 = ffma2(pack2(za.w, za.w), w, a0);
                    a1 = ffma2(pack2(zb.w, zb.w), w, a1);
                    a2 = ffma2(pack2(zc.w, zc.w), w, a2);
                    a3 = ffma2(pack2(zd.w, zd.w), w, a3);
                }
            }
            __syncthreads();
        }

        // ---- fold register update into elec ----
        {
            float x, y;
            float* dst;
            dst = s_elec + (rowb + 0) * DDIM + half + c2 * 2;
            unpack2(a0, x, y); dst[0] += x; dst[1] += y;
            dst = s_elec + (rowb + 1) * DDIM + half + c2 * 2;
            unpack2(a1, x, y); dst[0] += x; dst[1] += y;
            dst = s_elec + (rowb + 2) * DDIM + half + c2 * 2;
            unpack2(a2, x, y); dst[0] += x; dst[1] += y;
            dst = s_elec + (rowb + 3) * DDIM + half + c2 * 2;
            unpack2(a3, x, y); dst[0] += x; dst[1] += y;
        }
        __syncthreads();
    }

    // ---- write result ----
    for (int i = tid; i < NELEC * DDIM / 4; i += TPB)
        ((float4*)(out + b * NELEC * DDIM))[i] = ((const float4*)s_elec)[i];
}

extern "C" void kernel_launch(void* const* d_in, const int* in_sizes, int n_in,
                              void* d_out, int out_size) {
    const float* rs     = (const float*)d_in[0];
    const float* coords = (const float*)d_in[1];
    const float* Xtab   = (const float*)d_in[2];
    const float* Yw     = (const float*)d_in[3];
    const float* wW1    = (const float*)d_in[4];
    const float* wb1    = (const float*)d_in[5];
    const float* wW2    = (const float*)d_in[6];
    const float* h0tab  = (const float*)d_in[7];
    const float* hW     = (const float*)d_in[8];
    const float* gW     = (const float*)d_in[9];
    const int* same_s   = (const int*)d_in[10];
    const int* same_r   = (const int*)d_in[11];
    const int* anti_s   = (const int*)d_in[12];
    const int* anti_r   = (const int*)d_in[13];
    const int* ne_s     = (const int*)d_in[14];
    const int* ne_r     = (const int*)d_in[15];
    float* out = (float*)d_out;

    int B = in_sizes[0] / (NELEC * 3);

    cudaFuncSetAttribute(table_kernel,
                         cudaFuncAttributeMaxDynamicSharedMemorySize, TK_SMEM_FLOATS * 4);
    cudaFuncSetAttribute(schnet_kernel,
                         cudaFuncAttributeMaxDynamicSharedMemorySize, SMEM_BYTES);

    table_kernel<<<dim3(9, TGRID / 256), 256, TK_SMEM_FLOATS * 4>>>(wW1, wb1, wW2);
    csr_kernel<<<1, 32>>>(same_r, anti_r, ne_r);
    schnet_kernel<<<B, TPB, SMEM_BYTES>>>(rs, coords, Xtab, Yw, h0tab, hW, gW,
                                          same_s, same_r, anti_s, anti_r,
                                          ne_s, ne_r, out);
}

// round 9
// speedup vs baseline: 3.6573x; 1.0513x over previous
#include <cuda_runtime.h>

typedef unsigned long long u64;

#define NELEC 16
#define NNUC  4
#define DDIM  128
#define KDIM  64
#define FDIM  32
#define HDIM  45
#define E0    112
#define E1    128
#define E2    64
#define ETOT  304
#define TPB   256
#define PAD   68
#define TGRID 4096
#define TMAX  20.0f

// ---- shared memory layout (float offsets) ----
#define OFF_ELEC 0          // 2048
#define OFF_HX0  2048       // 16*68 = 1088
#define OFF_HX1  3136       // 16*68 = 1088
#define OFF_WEH  4224       // 128*68 = 8704 (also hW0 stage buffer)
#define OFF_Z    12928      // 16*68 = 1088
#define OFF_GH   14016      // 128*64 = 8192 (gW / hW1 stage buffer)
#define OFF_NUC  22208      // 4*68 = 272
#define OFF_D    22480      // 304
#define OFF_SEND 22784      // 304 ints
#define OFF_RS   23088      // 48
#define OFF_CO   23136      // 12
#define OFF_DEG  23148      // 48 ints
#define OFF_EDG  23196      // 384 ints
#define SMEM_FLOATS 23580
#define SMEM_BYTES (SMEM_FLOATS * 4)    // 94320 B -> 2 CTAs/SM

__device__ __forceinline__ u64 ffma2(u64 a, u64 b, u64 c) {
    u64 d; asm("fma.rn.f32x2 %0,%1,%2,%3;" : "=l"(d) : "l"(a), "l"(b), "l"(c)); return d;
}
__device__ __forceinline__ u64 pack2(float x, float y) {
    u64 r; asm("mov.b64 %0,{%1,%2};" : "=l"(r) : "f"(x), "f"(y)); return r;
}
__device__ __forceinline__ void unpack2(u64 v, float& x, float& y) {
    asm("mov.b64 {%0,%1},%2;" : "=f"(x), "=f"(y) : "l"(v));
}

// per-launch precomputed MLP table: we[lj][grid][k]  (9.4 MB, L2-resident)
__device__ float g_tab[9ULL * TGRID * KDIM];

// receiver CSR (LOCAL per-j edge indices), rebuilt every launch
__device__ int g_deg[3][NELEC];
__device__ int g_edge[3][NELEC][8];

__global__ void csr_kernel(const int* __restrict__ same_r,
                           const int* __restrict__ anti_r,
                           const int* __restrict__ ne_r) {
    if (blockIdx.x == 0 && threadIdx.x == 0) {
        for (int j = 0; j < 3; j++)
            for (int r = 0; r < NELEC; r++) g_deg[j][r] = 0;
        for (int e = 0; e < E0; e++) {
            int r = same_r[e]; int c = g_deg[0][r];
            if (c < 8) g_edge[0][r][c] = e;
            g_deg[0][r] = c + 1;
        }
        for (int e = 0; e < E1; e++) {
            int r = anti_r[e]; int c = g_deg[1][r];
            if (c < 8) g_edge[1][r][c] = e;
            g_deg[1][r] = c + 1;
        }
        for (int e = 0; e < E2; e++) {
            int r = ne_r[e]; int c = g_deg[2][r];
            if (c < 8) g_edge[2][r][c] = e;
            g_deg[2][r] = c + 1;
        }
    }
}

// ---- table precompute: we[k](d) on a uniform grid, per (l,j), packed fp32x2 ----
// dyn smem: W1 32*48=1536 | b1 48 | W2t 64*48=3072 | tile 256*68=17408 -> 22064 floats
#define TK_SMEM_FLOATS 22064
__global__ __launch_bounds__(256, 1)
void table_kernel(const float* __restrict__ wW1,
                  const float* __restrict__ wb1,
                  const float* __restrict__ wW2) {
    extern __shared__ float ts[];
    float* sW1  = ts;            // [32][48] padded
    float* sb1  = ts + 1536;     // [48] padded
    float* sW2t = ts + 1584;     // [64][48] padded, transposed
    float* tile = ts + 4656;     // [256][68]
    int lj = blockIdx.x;
    int tid = threadIdx.x;

    for (int i = tid; i < FDIM * HDIM; i += 256) {
        int f = i / HDIM, h = i - f * HDIM;
        sW1[f * 48 + h] = wW1[lj * FDIM * HDIM + i];
    }
    if (tid < HDIM) sb1[tid] = wb1[lj * HDIM + tid];
    for (int i = tid; i < HDIM * KDIM; i += 256) {
        int k = i / HDIM, h = i - k * HDIM;
        sW2t[k * 48 + h] = wW2[lj * HDIM * KDIM + h * KDIM + k];
    }
    // zero pad lanes
    for (int i = tid; i < FDIM; i += 256) {
        sW1[i * 48 + 45] = 0.f; sW1[i * 48 + 46] = 0.f; sW1[i * 48 + 47] = 0.f;
    }
    for (int i = tid; i < KDIM; i += 256) {
        sW2t[i * 48 + 45] = 0.f; sW2t[i * 48 + 46] = 0.f; sW2t[i * 48 + 47] = 0.f;
    }
    if (tid < 3) sb1[45 + tid] = 0.f;
    __syncthreads();

    int p = blockIdx.y * 256 + tid;
    float d = p * (TMAX / (float)(TGRID - 1));
    float env = d * d * __expf(-d);

    u64 hid2[24];
    {
        const ulonglong2* bv = (const ulonglong2*)sb1;
#pragma unroll
        for (int i = 0; i < 12; i++) {
            ulonglong2 bb = bv[i];
            hid2[2 * i] = bb.x; hid2[2 * i + 1] = bb.y;
        }
    }
#pragma unroll 4
    for (int f = 0; f < FDIM; f++) {
        float q = f * (1.0f / 31.0f);
        float mu = 10.0f * q * q;
        float sg = (1.0f + 10.0f * q) * (1.0f / 7.0f);
        float t = d - mu;
        float fe = env * __expf(-t * t / (sg * sg));
        u64 fe2 = pack2(fe, fe);
        const ulonglong2* w1f = (const ulonglong2*)(sW1 + f * 48);
#pragma unroll
        for (int h = 0; h < 12; h++) {
            ulonglong2 w = w1f[h];
            hid2[2 * h]     = ffma2(fe2, w.x, hid2[2 * h]);
            hid2[2 * h + 1] = ffma2(fe2, w.y, hid2[2 * h + 1]);
        }
    }
#pragma unroll
    for (int i = 0; i < 24; i++) {
        float x, y; unpack2(hid2[i], x, y);
        x = __fdividef(x, 1.0f + __expf(-x));
        y = __fdividef(y, 1.0f + __expf(-y));
        hid2[i] = pack2(x, y);
    }

    for (int kk = 0; kk < KDIM; kk += 4) {
        const ulonglong2* r0 = (const ulonglong2*)(sW2t + (kk + 0) * 48);
        const ulonglong2* r1 = (const ulonglong2*)(sW2t + (kk + 1) * 48);
        const ulonglong2* r2 = (const ulonglong2*)(sW2t + (kk + 2) * 48);
        const ulonglong2* r3 = (const ulonglong2*)(sW2t + (kk + 3) * 48);
        u64 p0 = 0, p1 = 0, p2 = 0, p3 = 0;
        u64 q0 = 0, q1 = 0, q2 = 0, q3 = 0;
#pragma unroll
        for (int h = 0; h < 12; h++) {
            u64 h0 = hid2[2 * h], h1 = hid2[2 * h + 1];
            ulonglong2 w0 = r0[h], w1 = r1[h], w2 = r2[h], w3 = r3[h];
            p0 = ffma2(h0, w0.x, p0); q0 = ffma2(h1, w0.y, q0);
            p1 = ffma2(h0, w1.x, p1); q1 = ffma2(h1, w1.y, q1);
            p2 = ffma2(h0, w2.x, p2); q2 = ffma2(h1, w2.y, q2);
            p3 = ffma2(h0, w3.x, p3); q3 = ffma2(h1, w3.y, q3);
        }
        float4 res;
        float ax_, bx_, cx_, dx_;
        unpack2(p0, ax_, bx_); unpack2(q0, cx_, dx_);
        res.x = (ax_ + bx_) + (cx_ + dx_);
        unpack2(p1, ax_, bx_); unpack2(q1, cx_, dx_);
        res.y = (ax_ + bx_) + (cx_ + dx_);
        unpack2(p2, ax_, bx_); unpack2(q2, cx_, dx_);
        res.z = (ax_ + bx_) + (cx_ + dx_);
        unpack2(p3, ax_, bx_); unpack2(q3, cx_, dx_);
        res.w = (ax_ + bx_) + (cx_ + dx_);
        *(float4*)(tile + tid * PAD + kk) = res;
    }
    __syncthreads();
    // coalesced write-out
    float4* dst = (float4*)(g_tab + ((size_t)lj * TGRID + blockIdx.y * 256) * KDIM);
    for (int i = tid; i < 256 * 16; i += 256) {
        int pl = i >> 4, k4 = i & 15;
        dst[pl * 16 + k4] = *(const float4*)(tile + pl * PAD + k4 * 4);
    }
}

__global__ __launch_bounds__(TPB, 2)
void schnet_kernel(const float* __restrict__ rs, const float* __restrict__ coords,
                   const float* __restrict__ Xtab, const float* __restrict__ Yw,
                   const float* __restrict__ h0tab, const float* __restrict__ hW,
                   const float* __restrict__ gW,
                   const int* __restrict__ same_s, const int* __restrict__ same_r,
                   const int* __restrict__ anti_s, const int* __restrict__ anti_r,
                   const int* __restrict__ ne_s, const int* __restrict__ ne_r,
                   float* __restrict__ out) {
    extern __shared__ float sm[];
    const int tid = threadIdx.x;
    const int b = blockIdx.x;

    float* s_elec = sm + OFF_ELEC;
    float* s_hx0  = sm + OFF_HX0;
    float* s_hx1  = sm + OFF_HX1;
    float* s_weh  = sm + OFF_WEH;
    float* s_z    = sm + OFF_Z;
    float* s_gh   = sm + OFF_GH;
    float* s_nuc  = sm + OFF_NUC;
    float* s_d    = sm + OFF_D;
    int*   s_send = (int*)(sm + OFF_SEND);
    float* s_rs   = sm + OFF_RS;
    float* s_co   = sm + OFF_CO;
    int*   s_deg  = (int*)(sm + OFF_DEG);
    int*   s_edg  = (int*)(sm + OFF_EDG);

    // ---- block init ----
    for (int i = tid; i < NELEC * 3; i += TPB) s_rs[i] = rs[b * NELEC * 3 + i];
    for (int i = tid; i < NNUC * 3; i += TPB) s_co[i] = coords[i];
    for (int i = tid; i < NELEC * DDIM; i += TPB) s_elec[i] = Xtab[i & (DDIM - 1)];
    for (int i = tid; i < NNUC * KDIM; i += TPB)
        s_nuc[(i >> 6) * PAD + (i & 63)] = Yw[i];
    for (int i = tid; i < E0; i += TPB) s_send[i] = same_s[i];
    for (int i = tid; i < E1; i += TPB) s_send[E0 + i] = anti_s[i];
    for (int i = tid; i < E2; i += TPB) s_send[E0 + E1 + i] = ne_s[i];
    for (int i = tid; i < 3 * NELEC; i += TPB) s_deg[i] = ((const int*)g_deg)[i];
    for (int i = tid; i < 3 * NELEC * 8; i += TPB) s_edg[i] = ((const int*)g_edge)[i];
    __syncthreads();

    // ---- edge distances ----
    for (int e = tid; e < ETOT; e += TPB) {
        int s = s_send[e];
        float ax, ay, az, bx, by, bz;
        if (e < E0 + E1) {
            int r = (e < E0) ? same_r[e] : anti_r[e - E0];
            ax = s_rs[s * 3 + 0]; ay = s_rs[s * 3 + 1]; az = s_rs[s * 3 + 2];
            bx = s_rs[r * 3 + 0]; by = s_rs[r * 3 + 1]; bz = s_rs[r * 3 + 2];
        } else {
            int r = ne_r[e - E0 - E1];
            ax = s_co[s * 3 + 0]; ay = s_co[s * 3 + 1]; az = s_co[s * 3 + 2];
            bx = s_rs[r * 3 + 0]; by = s_rs[r * 3 + 1]; bz = s_rs[r * 3 + 2];
        }
        float dx = ax - bx, dy = ay - by, dz = az - bz;
        s_d[e] = sqrtf(dx * dx + dy * dy + dz * dz);
    }
    __syncthreads();

    const int wid  = tid >> 5;
    const int c2   = tid & 31;
    const int rowb = (wid & 3) * 4;       // 4-row block
    const int half = (wid >> 2) * 64;     // column half for z@gW
    const int grow = rowb + (c2 >> 3);    // gather: this lane's z row
    const int gkb  = (c2 & 7) * 8;        // gather: this lane's k base (8 floats)

    // ================= layer loop =================
    for (int l = 0; l < 3; l++) {
        // ---- hx phase (both j=0,1 at once) ----
        if (l == 0) {
            for (int i = tid; i < NELEC * KDIM; i += TPB) {
                int r = i >> 6, k = i & 63;
                s_hx0[r * PAD + k] = h0tab[k];
                s_hx1[r * PAD + k] = h0tab[KDIM + k];
            }
            __syncthreads();
        } else {
            const float4* h0src = (const float4*)(hW + (size_t)((l - 1) * 2 + 0) * DDIM * KDIM);
            const float4* h1src = (const float4*)(hW + (size_t)((l - 1) * 2 + 1) * DDIM * KDIM);
            for (int i = tid; i < DDIM * KDIM / 4; i += TPB) {
                ((float4*)s_weh)[i] = h0src[i];
                ((float4*)s_gh)[i]  = h1src[i];
            }
            __syncthreads();
            {
                const float* hWs  = (wid >> 2) ? s_gh : s_weh;
                float* dsthx      = (wid >> 2) ? s_hx1 : s_hx0;
                u64 h0 = 0, h1 = 0, h2 = 0, h3 = 0;
                const float4* e0 = (const float4*)(s_elec + (rowb + 0) * DDIM);
                const float4* e1 = (const float4*)(s_elec + (rowb + 1) * DDIM);
                const float4* e2 = (const float4*)(s_elec + (rowb + 2) * DDIM);
                const float4* e3 = (const float4*)(s_elec + (rowb + 3) * DDIM);
                for (int d4 = 0; d4 < DDIM / 4; d4++) {
                    float4 va = e0[d4], vb = e1[d4], vc = e2[d4], vd = e3[d4];
                    u64 w0 = *(const u64*)(hWs + (d4 * 4 + 0) * KDIM + c2 * 2);
                    u64 w1 = *(const u64*)(hWs + (d4 * 4 + 1) * KDIM + c2 * 2);
                    u64 w2 = *(const u64*)(hWs + (d4 * 4 + 2) * KDIM + c2 * 2);
                    u64 w3 = *(const u64*)(hWs + (d4 * 4 + 3) * KDIM + c2 * 2);
                    h0 = ffma2(pack2(va.x, va.x), w0, h0);
                    h1 = ffma2(pack2(vb.x, vb.x), w0, h1);
                    h2 = ffma2(pack2(vc.x, vc.x), w0, h2);
                    h3 = ffma2(pack2(vd.x, vd.x), w0, h3);
                    h0 = ffma2(pack2(va.y, va.y), w1, h0);
                    h1 = ffma2(pack2(vb.y, vb.y), w1, h1);
                    h2 = ffma2(pack2(vc.y, vc.y), w1, h2);
                    h3 = ffma2(pack2(vd.y, vd.y), w1, h3);
                    h0 = ffma2(pack2(va.z, va.z), w2, h0);
                    h1 = ffma2(pack2(vb.z, vb.z), w2, h1);
                    h2 = ffma2(pack2(vc.z, vc.z), w2, h2);
                    h3 = ffma2(pack2(vd.z, vd.z), w2, h3);
                    h0 = ffma2(pack2(va.w, va.w), w3, h0);
                    h1 = ffma2(pack2(vb.w, vb.w), w3, h1);
                    h2 = ffma2(pack2(vc.w, vc.w), w3, h2);
                    h3 = ffma2(pack2(vd.w, vd.w), w3, h3);
                }
                *(u64*)(dsthx + (rowb + 0) * PAD + c2 * 2) = h0;
                *(u64*)(dsthx + (rowb + 1) * PAD + c2 * 2) = h1;
                *(u64*)(dsthx + (rowb + 2) * PAD + c2 * 2) = h2;
                *(u64*)(dsthx + (rowb + 3) * PAD + c2 * 2) = h3;
            }
            __syncthreads();
        }

        // persistent update accumulators across j
        u64 a0 = 0ULL, a1 = 0ULL, a2 = 0ULL, a3 = 0ULL;

        for (int j = 0; j < 3; j++) {
            int Ej, base;
            if (j == 0)      { Ej = E0; base = 0;       }
            else if (j == 1) { Ej = E1; base = E0;      }
            else             { Ej = E2; base = E0 + E1; }

            // ---- edge MLP (table lerp) || gW staging by idle threads ----
            if (tid < Ej) {
                float d = s_d[base + tid];
                float f = fminf(d, TMAX) * ((float)(TGRID - 1) / TMAX);
                int ii = (int)f;
                if (ii > TGRID - 2) ii = TGRID - 2;
                float fr = f - (float)ii;
                const float4* t0 = (const float4*)(g_tab + ((size_t)(l * 3 + j) * TGRID + ii) * KDIM);
                int snd = s_send[base + tid];
                const float* hx = ((j == 0) ? s_hx0 : (j == 1) ? s_hx1 : s_nuc) + snd * PAD;
                float* o = s_weh + tid * PAD;
#pragma unroll
                for (int k4 = 0; k4 < 16; k4++) {
                    float4 ta = __ldg(t0 + k4);
                    float4 tb = __ldg(t0 + 16 + k4);
                    float4 h4 = *(const float4*)(hx + k4 * 4);
                    float4 r;
                    r.x = fmaf(fr, tb.x - ta.x, ta.x) * h4.x;
                    r.y = fmaf(fr, tb.y - ta.y, ta.y) * h4.y;
                    r.z = fmaf(fr, tb.z - ta.z, ta.z) * h4.z;
                    r.w = fmaf(fr, tb.w - ta.w, ta.w) * h4.w;
                    *(float4*)(o + k4 * 4) = r;
                }
            } else {
                const float4* gsrc = (const float4*)(gW + (size_t)(l * 3 + j) * KDIM * DDIM);
                for (int i = tid - Ej; i < KDIM * DDIM / 4; i += TPB - Ej)
                    ((float4*)s_gh)[i] = gsrc[i];
            }
            __syncthreads();

            // ---- warp-local receiver gather: each warp builds the 4 z-rows
            //      its z@gW phase consumes (warp pairs duplicate identically) ----
            {
                int dg = s_deg[j * NELEC + grow];
                const int* er = s_edg + (j * NELEC + grow) * 8;
                float4 acc0 = make_float4(0.f, 0.f, 0.f, 0.f);
                float4 acc1 = make_float4(0.f, 0.f, 0.f, 0.f);
                for (int i = 0; i < dg; i++) {
                    const float* p = s_weh + er[i] * PAD + gkb;
                    float4 v0 = *(const float4*)(p);
                    float4 v1 = *(const float4*)(p + 4);
                    acc0.x += v0.x; acc0.y += v0.y; acc0.z += v0.z; acc0.w += v0.w;
                    acc1.x += v1.x; acc1.y += v1.y; acc1.z += v1.z; acc1.w += v1.w;
                }
                *(float4*)(s_z + grow * PAD + gkb)     = acc0;
                *(float4*)(s_z + grow * PAD + gkb + 4) = acc1;
            }
            __syncwarp();

            // ---- z @ gW : 4 rows per warp, 64-col half, u64 lanes ----
            {
                const float4* z0 = (const float4*)(s_z + (rowb + 0) * PAD);
                const float4* z1 = (const float4*)(s_z + (rowb + 1) * PAD);
                const float4* z2 = (const float4*)(s_z + (rowb + 2) * PAD);
                const float4* z3 = (const float4*)(s_z + (rowb + 3) * PAD);
#pragma unroll 2
                for (int k4 = 0; k4 < 16; k4++) {
                    float4 za = z0[k4], zb = z1[k4], zc = z2[k4], zd = z3[k4];
                    u64 w;
                    w = *(const u64*)(s_gh + (k4 * 4 + 0) * DDIM + half + c2 * 2);
                    a0 = ffma2(pack2(za.x, za.x), w, a0);
                    a1 = ffma2(pack2(zb.x, zb.x), w, a1);
                    a2 = ffma2(pack2(zc.x, zc.x), w, a2);
                    a3 = ffma2(pack2(zd.x, zd.x), w, a3);
                    w = *(const u64*)(s_gh + (k4 * 4 + 1) * DDIM + half + c2 * 2);
                    a0 = ffma2(pack2(za.y, za.y), w, a0);
                    a1 = ffma2(pack2(zb.y, zb.y), w, a1);
                    a2 = ffma2(pack2(zc.y, zc.y), w, a2);
                    a3 = ffma2(pack2(zd.y, zd.y), w, a3);
                    w = *(const u64*)(s_gh + (k4 * 4 + 2) * DDIM + half + c2 * 2);
                    a0 = ffma2(pack2(za.z, za.z), w, a0);
                    a1 = ffma2(pack2(zb.z, zb.z), w, a1);
                    a2 = ffma2(pack2(zc.z, zc.z), w, a2);
                    a3 = ffma2(pack2(zd.z, zd.z), w, a3);
                    w = *(const u64*)(s_gh + (k4 * 4 + 3) * DDIM + half + c2 * 2);
                    a0 = ffma2(pack2(za.w, za.w), w, a0);
                    a1 = ffma2(pack2(zb.w, zb.w), w, a1);
                    a2 = ffma2(pack2(zc.w, zc.w), w, a2);
                    a3 = ffma2(pack2(zd.w, zd.w), w, a3);
                }
            }
            __syncthreads();
        }

        // ---- fold register update into elec ----
        {
            float x, y;
            float* dst;
            dst = s_elec + (rowb + 0) * DDIM + half + c2 * 2;
            unpack2(a0, x, y); dst[0] += x; dst[1] += y;
            dst = s_elec + (rowb + 1) * DDIM + half + c2 * 2;
            unpack2(a1, x, y); dst[0] += x; dst[1] += y;
            dst = s_elec + (rowb + 2) * DDIM + half + c2 * 2;
            unpack2(a2, x, y); dst[0] += x; dst[1] += y;
            dst = s_elec + (rowb + 3) * DDIM + half + c2 * 2;
            unpack2(a3, x, y); dst[0] += x; dst[1] += y;
        }
        __syncthreads();
    }

    // ---- write result ----
    for (int i = tid; i < NELEC * DDIM / 4; i += TPB)
        ((float4*)(out + b * NELEC * DDIM))[i] = ((const float4*)s_elec)[i];
}

extern "C" void kernel_launch(void* const* d_in, const int* in_sizes, int n_in,
                              void* d_out, int out_size) {
    const float* rs     = (const float*)d_in[0];
    const float* coords = (const float*)d_in[1];
    const float* Xtab   = (const float*)d_in[2];
    const float* Yw     = (const float*)d_in[3];
    const float* wW1    = (const float*)d_in[4];
    const float* wb1    = (const float*)d_in[5];
    const float* wW2    = (const float*)d_in[6];
    const float* h0tab  = (const float*)d_in[7];
    const float* hW     = (const float*)d_in[8];
    const float* gW     = (const float*)d_in[9];
    const int* same_s   = (const int*)d_in[10];
    const int* same_r   = (const int*)d_in[11];
    const int* anti_s   = (const int*)d_in[12];
    const int* anti_r   = (const int*)d_in[13];
    const int* ne_s     = (const int*)d_in[14];
    const int* ne_r     = (const int*)d_in[15];
    float* out = (float*)d_out;

    int B = in_sizes[0] / (NELEC * 3);

    cudaFuncSetAttribute(table_kernel,
                         cudaFuncAttributeMaxDynamicSharedMemorySize, TK_SMEM_FLOATS * 4);
    cudaFuncSetAttribute(schnet_kernel,
                         cudaFuncAttributeMaxDynamicSharedMemorySize, SMEM_BYTES);

    table_kernel<<<dim3(9, TGRID / 256), 256, TK_SMEM_FLOATS * 4>>>(wW1, wb1, wW2);
    csr_kernel<<<1, 32>>>(same_r, anti_r, ne_r);
    schnet_kernel<<<B, TPB, SMEM_BYTES>>>(rs, coords, Xtab, Yw, h0tab, hW, gW,
                                          same_s, same_r, anti_s, anti_r,
                                          ne_s, ne_r, out);
}

// round 10
// speedup vs baseline: 4.3039x; 1.1768x over previous
#include <cuda_runtime.h>

typedef unsigned long long u64;

#define NELEC 16
#define NNUC  4
#define DDIM  128
#define KDIM  64
#define FDIM  32
#define HDIM  45
#define E0    112
#define E1    128
#define E2    64
#define ETOT  304
#define TPB   512
#define PAD   68
#define TGRID 4096
#define TMAX  20.0f

// per-elem strides
#define ELEC_S 2048
#define HX_S   1088
#define WEH_S  8704
#define Z_S    1088

// ---- shared memory layout (float offsets), 2 batch elems per CTA ----
#define OFF_ELEC 0           // 2*2048 = 4096
#define OFF_HX0  4096        // 2*1088 = 2176
#define OFF_HX1  6272        // 2*1088 = 2176
#define OFF_WEH  8448        // 2*8704 = 17408 (elem0 region doubles as hW0 stage)
#define OFF_Z    25856       // 2*1088 = 2176
#define OFF_GH   28032       // 8192 (gW / hW1 stage, shared)
#define OFF_NUC  36224       // 272
#define OFF_D    36496       // 2*304 = 608
#define OFF_SEND 37104       // 304 ints
#define OFF_RS   37408       // 2*48 = 96
#define OFF_CO   37504       // 12
#define OFF_DEG  37516       // 48 ints
#define OFF_EDG  37564       // 384 ints
#define SMEM_FLOATS 37948
#define SMEM_BYTES (SMEM_FLOATS * 4)    // 151792 B -> 1 CTA/SM

__device__ __forceinline__ u64 ffma2(u64 a, u64 b, u64 c) {
    u64 d; asm("fma.rn.f32x2 %0,%1,%2,%3;" : "=l"(d) : "l"(a), "l"(b), "l"(c)); return d;
}
__device__ __forceinline__ u64 pack2(float x, float y) {
    u64 r; asm("mov.b64 %0,{%1,%2};" : "=l"(r) : "f"(x), "f"(y)); return r;
}
__device__ __forceinline__ void unpack2(u64 v, float& x, float& y) {
    asm("mov.b64 {%0,%1},%2;" : "=f"(x), "=f"(y) : "l"(v));
}

// per-launch precomputed MLP table: we[lj][grid][k]  (9.4 MB, L2-resident)
__device__ float g_tab[9ULL * TGRID * KDIM];

// receiver CSR (LOCAL per-j edge indices), rebuilt every launch
__device__ int g_deg[3][NELEC];
__device__ int g_edge[3][NELEC][8];

__global__ void csr_kernel(const int* __restrict__ same_r,
                           const int* __restrict__ anti_r,
                           const int* __restrict__ ne_r) {
    if (blockIdx.x == 0 && threadIdx.x == 0) {
        for (int j = 0; j < 3; j++)
            for (int r = 0; r < NELEC; r++) g_deg[j][r] = 0;
        for (int e = 0; e < E0; e++) {
            int r = same_r[e]; int c = g_deg[0][r];
            if (c < 8) g_edge[0][r][c] = e;
            g_deg[0][r] = c + 1;
        }
        for (int e = 0; e < E1; e++) {
            int r = anti_r[e]; int c = g_deg[1][r];
            if (c < 8) g_edge[1][r][c] = e;
            g_deg[1][r] = c + 1;
        }
        for (int e = 0; e < E2; e++) {
            int r = ne_r[e]; int c = g_deg[2][r];
            if (c < 8) g_edge[2][r][c] = e;
            g_deg[2][r] = c + 1;
        }
    }
}

// ---- table precompute: we[k](d) on a uniform grid, per (l,j), packed fp32x2 ----
#define TK_SMEM_FLOATS 22064
__global__ __launch_bounds__(256, 1)
void table_kernel(const float* __restrict__ wW1,
                  const float* __restrict__ wb1,
                  const float* __restrict__ wW2) {
    extern __shared__ float ts[];
    float* sW1  = ts;            // [32][48] padded
    float* sb1  = ts + 1536;     // [48] padded
    float* sW2t = ts + 1584;     // [64][48] padded, transposed
    float* tile = ts + 4656;     // [256][68]
    int lj = blockIdx.x;
    int tid = threadIdx.x;

    for (int i = tid; i < FDIM * HDIM; i += 256) {
        int f = i / HDIM, h = i - f * HDIM;
        sW1[f * 48 + h] = wW1[lj * FDIM * HDIM + i];
    }
    if (tid < HDIM) sb1[tid] = wb1[lj * HDIM + tid];
    for (int i = tid; i < HDIM * KDIM; i += 256) {
        int k = i / HDIM, h = i - k * HDIM;
        sW2t[k * 48 + h] = wW2[lj * HDIM * KDIM + h * KDIM + k];
    }
    for (int i = tid; i < FDIM; i += 256) {
        sW1[i * 48 + 45] = 0.f; sW1[i * 48 + 46] = 0.f; sW1[i * 48 + 47] = 0.f;
    }
    for (int i = tid; i < KDIM; i += 256) {
        sW2t[i * 48 + 45] = 0.f; sW2t[i * 48 + 46] = 0.f; sW2t[i * 48 + 47] = 0.f;
    }
    if (tid < 3) sb1[45 + tid] = 0.f;
    __syncthreads();

    int p = blockIdx.y * 256 + tid;
    float d = p * (TMAX / (float)(TGRID - 1));
    float env = d * d * __expf(-d);

    u64 hid2[24];
    {
        const ulonglong2* bv = (const ulonglong2*)sb1;
#pragma unroll
        for (int i = 0; i < 12; i++) {
            ulonglong2 bb = bv[i];
            hid2[2 * i] = bb.x; hid2[2 * i + 1] = bb.y;
        }
    }
#pragma unroll 4
    for (int f = 0; f < FDIM; f++) {
        float q = f * (1.0f / 31.0f);
        float mu = 10.0f * q * q;
        float sg = (1.0f + 10.0f * q) * (1.0f / 7.0f);
        float t = d - mu;
        float fe = env * __expf(-t * t / (sg * sg));
        u64 fe2 = pack2(fe, fe);
        const ulonglong2* w1f = (const ulonglong2*)(sW1 + f * 48);
#pragma unroll
        for (int h = 0; h < 12; h++) {
            ulonglong2 w = w1f[h];
            hid2[2 * h]     = ffma2(fe2, w.x, hid2[2 * h]);
            hid2[2 * h + 1] = ffma2(fe2, w.y, hid2[2 * h + 1]);
        }
    }
#pragma unroll
    for (int i = 0; i < 24; i++) {
        float x, y; unpack2(hid2[i], x, y);
        x = __fdividef(x, 1.0f + __expf(-x));
        y = __fdividef(y, 1.0f + __expf(-y));
        hid2[i] = pack2(x, y);
    }

    for (int kk = 0; kk < KDIM; kk += 4) {
        const ulonglong2* r0 = (const ulonglong2*)(sW2t + (kk + 0) * 48);
        const ulonglong2* r1 = (const ulonglong2*)(sW2t + (kk + 1) * 48);
        const ulonglong2* r2 = (const ulonglong2*)(sW2t + (kk + 2) * 48);
        const ulonglong2* r3 = (const ulonglong2*)(sW2t + (kk + 3) * 48);
        u64 p0 = 0, p1 = 0, p2 = 0, p3 = 0;
        u64 q0 = 0, q1 = 0, q2 = 0, q3 = 0;
#pragma unroll
        for (int h = 0; h < 12; h++) {
            u64 h0 = hid2[2 * h], h1 = hid2[2 * h + 1];
            ulonglong2 w0 = r0[h], w1 = r1[h], w2 = r2[h], w3 = r3[h];
            p0 = ffma2(h0, w0.x, p0); q0 = ffma2(h1, w0.y, q0);
            p1 = ffma2(h0, w1.x, p1); q1 = ffma2(h1, w1.y, q1);
            p2 = ffma2(h0, w2.x, p2); q2 = ffma2(h1, w2.y, q2);
            p3 = ffma2(h0, w3.x, p3); q3 = ffma2(h1, w3.y, q3);
        }
        float4 res;
        float ax_, bx_, cx_, dx_;
        unpack2(p0, ax_, bx_); unpack2(q0, cx_, dx_);
        res.x = (ax_ + bx_) + (cx_ + dx_);
        unpack2(p1, ax_, bx_); unpack2(q1, cx_, dx_);
        res.y = (ax_ + bx_) + (cx_ + dx_);
        unpack2(p2, ax_, bx_); unpack2(q2, cx_, dx_);
        res.z = (ax_ + bx_) + (cx_ + dx_);
        unpack2(p3, ax_, bx_); unpack2(q3, cx_, dx_);
        res.w = (ax_ + bx_) + (cx_ + dx_);
        *(float4*)(tile + tid * PAD + kk) = res;
    }
    __syncthreads();
    float4* dst = (float4*)(g_tab + ((size_t)lj * TGRID + blockIdx.y * 256) * KDIM);
    for (int i = tid; i < 256 * 16; i += 256) {
        int pl = i >> 4, k4 = i & 15;
        dst[pl * 16 + k4] = *(const float4*)(tile + pl * PAD + k4 * 4);
    }
}

__global__ __launch_bounds__(TPB, 1)
void schnet_kernel(const float* __restrict__ rs, const float* __restrict__ coords,
                   const float* __restrict__ Xtab, const float* __restrict__ Yw,
                   const float* __restrict__ h0tab, const float* __restrict__ hW,
                   const float* __restrict__ gW,
                   const int* __restrict__ same_s, const int* __restrict__ same_r,
                   const int* __restrict__ anti_s, const int* __restrict__ anti_r,
                   const int* __restrict__ ne_s, const int* __restrict__ ne_r,
                   float* __restrict__ out) {
    extern __shared__ float sm[];
    const int tid = threadIdx.x;
    const int b0 = blockIdx.x * 2;   // two batch elems per CTA

    float* s_elec = sm + OFF_ELEC;
    float* s_hx0  = sm + OFF_HX0;
    float* s_hx1  = sm + OFF_HX1;
    float* s_weh  = sm + OFF_WEH;
    float* s_z    = sm + OFF_Z;
    float* s_gh   = sm + OFF_GH;
    float* s_nuc  = sm + OFF_NUC;
    float* s_d    = sm + OFF_D;
    int*   s_send = (int*)(sm + OFF_SEND);
    float* s_rs   = sm + OFF_RS;
    float* s_co   = sm + OFF_CO;
    int*   s_deg  = (int*)(sm + OFF_DEG);
    int*   s_edg  = (int*)(sm + OFF_EDG);

    // ---- block init ----
    for (int i = tid; i < 2 * NELEC * 3; i += TPB) s_rs[i] = rs[b0 * NELEC * 3 + i];
    for (int i = tid; i < NNUC * 3; i += TPB) s_co[i] = coords[i];
    for (int i = tid; i < 2 * NELEC * DDIM; i += TPB) s_elec[i] = Xtab[i & (DDIM - 1)];
    for (int i = tid; i < NNUC * KDIM; i += TPB)
        s_nuc[(i >> 6) * PAD + (i & 63)] = Yw[i];
    for (int i = tid; i < E0; i += TPB) s_send[i] = same_s[i];
    for (int i = tid; i < E1; i += TPB) s_send[E0 + i] = anti_s[i];
    for (int i = tid; i < E2; i += TPB) s_send[E0 + E1 + i] = ne_s[i];
    for (int i = tid; i < 3 * NELEC; i += TPB) s_deg[i] = ((const int*)g_deg)[i];
    for (int i = tid; i < 3 * NELEC * 8; i += TPB) s_edg[i] = ((const int*)g_edge)[i];
    __syncthreads();

    // ---- edge distances (both elems) ----
    for (int ee = tid; ee < 2 * ETOT; ee += TPB) {
        int eb = (ee < ETOT) ? 0 : 1;
        int e = ee - eb * ETOT;
        const float* rsE = s_rs + eb * 48;
        int s = s_send[e];
        float ax, ay, az, bx, by, bz;
        if (e < E0 + E1) {
            int r = (e < E0) ? same_r[e] : anti_r[e - E0];
            ax = rsE[s * 3 + 0]; ay = rsE[s * 3 + 1]; az = rsE[s * 3 + 2];
            bx = rsE[r * 3 + 0]; by = rsE[r * 3 + 1]; bz = rsE[r * 3 + 2];
        } else {
            int r = ne_r[e - E0 - E1];
            ax = s_co[s * 3 + 0]; ay = s_co[s * 3 + 1]; az = s_co[s * 3 + 2];
            bx = rsE[r * 3 + 0]; by = rsE[r * 3 + 1]; bz = rsE[r * 3 + 2];
        }
        float dx = ax - bx, dy = ay - by, dz = az - bz;
        s_d[ee] = sqrtf(dx * dx + dy * dy + dz * dz);
    }
    __syncthreads();

    const int wid  = tid >> 5;
    const int c2   = tid & 31;
    const int web  = wid >> 3;            // warp's batch elem
    const int sw   = wid & 7;             // role within elem
    const int rowb = (sw & 3) * 4;        // 4-row block
    const int half = (sw >> 2) * 64;      // column half
    float* elecE = s_elec + web * ELEC_S;
    float* zE    = s_z + web * Z_S;

    // ================= layer loop =================
    for (int l = 0; l < 3; l++) {
        // ---- hx phase (both j=0,1, both elems) ----
        if (l == 0) {
            for (int i = tid; i < 2 * NELEC * KDIM; i += TPB) {
                int eb = i >> 10, r = (i >> 6) & 15, k = i & 63;
                s_hx0[eb * HX_S + r * PAD + k] = h0tab[k];
                s_hx1[eb * HX_S + r * PAD + k] = h0tab[KDIM + k];
            }
            __syncthreads();
        } else {
            const float4* h0src = (const float4*)(hW + (size_t)((l - 1) * 2 + 0) * DDIM * KDIM);
            const float4* h1src = (const float4*)(hW + (size_t)((l - 1) * 2 + 1) * DDIM * KDIM);
            for (int i = tid; i < DDIM * KDIM / 4; i += TPB) {
                ((float4*)s_weh)[i] = h0src[i];     // elem0 weh region = hW0 stage
                ((float4*)s_gh)[i]  = h1src[i];     // gh = hW1 stage
            }
            __syncthreads();
            {
                const float* hWs = (sw >> 2) ? s_gh : s_weh;
                float* dsthx     = ((sw >> 2) ? s_hx1 : s_hx0) + web * HX_S;
                u64 h0 = 0, h1 = 0, h2 = 0, h3 = 0;
                const float4* e0 = (const float4*)(elecE + (rowb + 0) * DDIM);
                const float4* e1 = (const float4*)(elecE + (rowb + 1) * DDIM);
                const float4* e2 = (const float4*)(elecE + (rowb + 2) * DDIM);
                const float4* e3 = (const float4*)(elecE + (rowb + 3) * DDIM);
                for (int d4 = 0; d4 < DDIM / 4; d4++) {
                    float4 va = e0[d4], vb = e1[d4], vc = e2[d4], vd = e3[d4];
                    u64 w0 = *(const u64*)(hWs + (d4 * 4 + 0) * KDIM + c2 * 2);
                    u64 w1 = *(const u64*)(hWs + (d4 * 4 + 1) * KDIM + c2 * 2);
                    u64 w2 = *(const u64*)(hWs + (d4 * 4 + 2) * KDIM + c2 * 2);
                    u64 w3 = *(const u64*)(hWs + (d4 * 4 + 3) * KDIM + c2 * 2);
                    h0 = ffma2(pack2(va.x, va.x), w0, h0);
                    h1 = ffma2(pack2(vb.x, vb.x), w0, h1);
                    h2 = ffma2(pack2(vc.x, vc.x), w0, h2);
                    h3 = ffma2(pack2(vd.x, vd.x), w0, h3);
                    h0 = ffma2(pack2(va.y, va.y), w1, h0);
                    h1 = ffma2(pack2(vb.y, vb.y), w1, h1);
                    h2 = ffma2(pack2(vc.y, vc.y), w1, h2);
                    h3 = ffma2(pack2(vd.y, vd.y), w1, h3);
                    h0 = ffma2(pack2(va.z, va.z), w2, h0);
                    h1 = ffma2(pack2(vb.z, vb.z), w2, h1);
                    h2 = ffma2(pack2(vc.z, vc.z), w2, h2);
                    h3 = ffma2(pack2(vd.z, vd.z), w2, h3);
                    h0 = ffma2(pack2(va.w, va.w), w3, h0);
                    h1 = ffma2(pack2(vb.w, vb.w), w3, h1);
                    h2 = ffma2(pack2(vc.w, vc.w), w3, h2);
                    h3 = ffma2(pack2(vd.w, vd.w), w3, h3);
                }
                *(u64*)(dsthx + (rowb + 0) * PAD + c2 * 2) = h0;
                *(u64*)(dsthx + (rowb + 1) * PAD + c2 * 2) = h1;
                *(u64*)(dsthx + (rowb + 2) * PAD + c2 * 2) = h2;
                *(u64*)(dsthx + (rowb + 3) * PAD + c2 * 2) = h3;
            }
            __syncthreads();
        }

        // persistent update accumulators across j
        u64 a0 = 0ULL, a1 = 0ULL, a2 = 0ULL, a3 = 0ULL;

        for (int j = 0; j < 3; j++) {
            int Ej, base;
            if (j == 0)      { Ej = E0; base = 0;       }
            else if (j == 1) { Ej = E1; base = E0;      }
            else             { Ej = E2; base = E0 + E1; }
            int nact = 2 * Ej;

            // ---- edge MLP (table lerp, both elems) || gW staging by idle threads ----
            if (tid < nact) {
                int eb, e;
                if (j == 0)      { eb = tid / E0; e = tid - eb * E0; }
                else if (j == 1) { eb = tid >> 7; e = tid & 127; }
                else             { eb = tid >> 6; e = tid & 63; }
                float d = s_d[eb * ETOT + base + e];
                float f = fminf(d, TMAX) * ((float)(TGRID - 1) / TMAX);
                int ii = (int)f;
                if (ii > TGRID - 2) ii = TGRID - 2;
                float fr = f - (float)ii;
                const float4* t0 = (const float4*)(g_tab + ((size_t)(l * 3 + j) * TGRID + ii) * KDIM);
                int snd = s_send[base + e];
                const float* hxb;
                if (j == 0)      hxb = s_hx0 + eb * HX_S;
                else if (j == 1) hxb = s_hx1 + eb * HX_S;
                else             hxb = s_nuc;
                const float* hx = hxb + snd * PAD;
                float* o = s_weh + eb * WEH_S + e * PAD;
#pragma unroll
                for (int k4 = 0; k4 < 16; k4++) {
                    float4 ta = __ldg(t0 + k4);
                    float4 tb = __ldg(t0 + 16 + k4);
                    float4 h4 = *(const float4*)(hx + k4 * 4);
                    float4 r;
                    r.x = fmaf(fr, tb.x - ta.x, ta.x) * h4.x;
                    r.y = fmaf(fr, tb.y - ta.y, ta.y) * h4.y;
                    r.z = fmaf(fr, tb.z - ta.z, ta.z) * h4.z;
                    r.w = fmaf(fr, tb.w - ta.w, ta.w) * h4.w;
                    *(float4*)(o + k4 * 4) = r;
                }
            } else {
                const float4* gsrc = (const float4*)(gW + (size_t)(l * 3 + j) * KDIM * DDIM);
                for (int i = tid - nact; i < KDIM * DDIM / 4; i += TPB - nact)
                    ((float4*)s_gh)[i] = gsrc[i];
            }
            __syncthreads();

            // ---- receiver gather into z (half-warp per row, distinct, both elems) ----
            {
                int t = tid & 255, eb = tid >> 8;
                int rr = t >> 4, cc = t & 15;
                const float* wehE = s_weh + eb * WEH_S;
                int dg = s_deg[j * NELEC + rr];
                const int* er = s_edg + (j * NELEC + rr) * 8;
                float4 acc = make_float4(0.f, 0.f, 0.f, 0.f);
                for (int i = 0; i < dg; i++) {
                    float4 v = *(const float4*)(wehE + er[i] * PAD + cc * 4);
                    acc.x += v.x; acc.y += v.y; acc.z += v.z; acc.w += v.w;
                }
                *(float4*)(s_z + eb * Z_S + rr * PAD + cc * 4) = acc;
            }
            __syncthreads();

            // ---- z @ gW : per warp 4 rows × 64-col half of its elem ----
            {
                const float4* z0 = (const float4*)(zE + (rowb + 0) * PAD);
                const float4* z1 = (const float4*)(zE + (rowb + 1) * PAD);
                const float4* z2 = (const float4*)(zE + (rowb + 2) * PAD);
                const float4* z3 = (const float4*)(zE + (rowb + 3) * PAD);
#pragma unroll 2
                for (int k4 = 0; k4 < 16; k4++) {
                    float4 za = z0[k4], zb = z1[k4], zc = z2[k4], zd = z3[k4];
                    u64 w;
                    w = *(const u64*)(s_gh + (k4 * 4 + 0) * DDIM + half + c2 * 2);
                    a0 = ffma2(pack2(za.x, za.x), w, a0);
                    a1 = ffma2(pack2(zb.x, zb.x), w, a1);
                    a2 = ffma2(pack2(zc.x, zc.x), w, a2);
                    a3 = ffma2(pack2(zd.x, zd.x), w, a3);
                    w = *(const u64*)(s_gh + (k4 * 4 + 1) * DDIM + half + c2 * 2);
                    a0 = ffma2(pack2(za.y, za.y), w, a0);
                    a1 = ffma2(pack2(zb.y, zb.y), w, a1);
                    a2 = ffma2(pack2(zc.y, zc.y), w, a2);
                    a3 = ffma2(pack2(zd.y, zd.y), w, a3);
                    w = *(const u64*)(s_gh + (k4 * 4 + 2) * DDIM + half + c2 * 2);
                    a0 = ffma2(pack2(za.z, za.z), w, a0);
                    a1 = ffma2(pack2(zb.z, zb.z), w, a1);
                    a2 = ffma2(pack2(zc.z, zc.z), w, a2);
                    a3 = ffma2(pack2(zd.z, zd.z), w, a3);
                    w = *(const u64*)(s_gh + (k4 * 4 + 3) * DDIM + half + c2 * 2);
                    a0 = ffma2(pack2(za.w, za.w), w, a0);
                    a1 = ffma2(pack2(zb.w, zb.w), w, a1);
                    a2 = ffma2(pack2(zc.w, zc.w), w, a2);
                    a3 = ffma2(pack2(zd.w, zd.w), w, a3);
                }
            }
            __syncthreads();
        }

        // ---- fold register update into elec ----
        {
            float x, y;
            float* dst;
            dst = elecE + (rowb + 0) * DDIM + half + c2 * 2;
            unpack2(a0, x, y); dst[0] += x; dst[1] += y;
            dst = elecE + (rowb + 1) * DDIM + half + c2 * 2;
            unpack2(a1, x, y); dst[0] += x; dst[1] += y;
            dst = elecE + (rowb + 2) * DDIM + half + c2 * 2;
            unpack2(a2, x, y); dst[0] += x; dst[1] += y;
            dst = elecE + (rowb + 3) * DDIM + half + c2 * 2;
            unpack2(a3, x, y); dst[0] += x; dst[1] += y;
        }
        __syncthreads();
    }

    // ---- write result (both elems contiguous) ----
    for (int i = tid; i < 2 * NELEC * DDIM / 4; i += TPB)
        ((float4*)(out + b0 * NELEC * DDIM))[i] = ((const float4*)s_elec)[i];
}

extern "C" void kernel_launch(void* const* d_in, const int* in_sizes, int n_in,
                              void* d_out, int out_size) {
    const float* rs     = (const float*)d_in[0];
    const float* coords = (const float*)d_in[1];
    const float* Xtab   = (const float*)d_in[2];
    const float* Yw     = (const float*)d_in[3];
    const float* wW1    = (const float*)d_in[4];
    const float* wb1    = (const float*)d_in[5];
    const float* wW2    = (const float*)d_in[6];
    const float* h0tab  = (const float*)d_in[7];
    const float* hW     = (const float*)d_in[8];
    const float* gW     = (const float*)d_in[9];
    const int* same_s   = (const int*)d_in[10];
    const int* same_r   = (const int*)d_in[11];
    const int* anti_s   = (const int*)d_in[12];
    const int* anti_r   = (const int*)d_in[13];
    const int* ne_s     = (const int*)d_in[14];
    const int* ne_r     = (const int*)d_in[15];
    float* out = (float*)d_out;

    int B = in_sizes[0] / (NELEC * 3);

    cudaFuncSetAttribute(table_kernel,
                         cudaFuncAttributeMaxDynamicSharedMemorySize, TK_SMEM_FLOATS * 4);
    cudaFuncSetAttribute(schnet_kernel,
                         cudaFuncAttributeMaxDynamicSharedMemorySize, SMEM_BYTES);

    table_kernel<<<dim3(9, TGRID / 256), 256, TK_SMEM_FLOATS * 4>>>(wW1, wb1, wW2);
    csr_kernel<<<1, 32>>>(same_r, anti_r, ne_r);
    schnet_kernel<<<B / 2, TPB, SMEM_BYTES>>>(rs, coords, Xtab, Yw, h0tab, hW, gW,
                                              same_s, same_r, anti_s, anti_r,
                                              ne_s, ne_r, out);
}